// round 9
// baseline (speedup 1.0000x reference)
#include <cuda_runtime.h>
#include <math.h>

#define TT 256
#define DD 64
#define SS 64
#define VV 32
#define BPB 8            // batches per block (kernel 1)
#define K2B 4            // batches per block (kernel 2)
#define LCAP 2048        // shared list capacity (map front, step back)

typedef unsigned long long u64;

// per-batch intermediate: [0:64) wsum, [64:96) accv
__device__ float g_scratch[4096 * 96];

// ---------------- kernel 1 shared layout (floats) ----------------
#define OFF_W1M   0        // 4096 quad-interleaved
#define OFF_W1S   4096     // 4096
#define OFF_B1M   8192     // 64
#define OFF_W2M   8256     // 64
#define OFF_B1S   8320     // 64
#define OFF_W2S   8384     // 64
#define OFF_LIST  8448     // 2048 ints shared (map front / step back)
#define OFF_GAIN  10496    // 2048 floats shared (aligned with LIST)
#define OFF_X     12544    // 8 warps * 8 tok * 64 = 4096
#define OFF_WALK  16640    // 8*64
#define OFF_NW    17152    // 8*64
#define OFF_WSUM  17664    // 8*64
#define OFF_ACCV  18176    // 8*32
#define OFF_CNT   18432    // 2 ints
#define SMEM1_FLOATS 18436

__device__ __forceinline__ float gelu_exact(float x) {
    return 0.5f * x * (1.0f + erff(x * 0.70710678118654752440f));
}

__device__ __forceinline__ u64 ffma2(u64 a, u64 b, u64 c) {
    u64 d;
    asm("fma.rn.f32x2 %0, %1, %2, %3;" : "=l"(d) : "l"(a), "l"(b), "l"(c));
    return d;
}
__device__ __forceinline__ u64 packdup(float x) {
    u64 d;
    asm("mov.b64 %0, {%1, %1};" : "=l"(d) : "f"(x));
    return d;
}

// warp-cooperative gate MLP, 8 tokens/pass, gather pipelined one pass ahead.
// Quad weight layout: Wq[kq*256 + f*4 + j] = W[4kq+j][f]
// lane l owns features l and l+32; acc u64 = (even-k partial, odd-k partial)
// item: tok[0:8) | bi[8:11) | src[11:17) | tgt[17:23)
__device__ __forceinline__ void process_events8(
    const int* __restrict__ list, int n, float b2,
    float* __restrict__ gout,
    const float* __restrict__ sWq, const float* __restrict__ sb1,
    const float* __restrict__ sw2,
    const float* __restrict__ evidence, int b0,
    float* __restrict__ sXw, int lane)
{
    const int wid = threadIdx.x >> 5;
    const int sel = lane >> 4;           // 0: even token of pair, 1: odd
    const int sub = lane & 15;           // 16B chunk within row

    const float b1a = sb1[lane], b1b = sb1[lane + 32];
    const float w2a = sw2[lane], w2b = sw2[lane + 32];

    int items[8];
    bool valid[8];
    float4 vreg[4];

    int base = wid * 8;
    if (base < n) {
#pragma unroll
        for (int i = 0; i < 8; i++) {
            int idx = base + i;
            valid[i] = (idx < n);
            items[i] = list[valid[i] ? idx : (n - 1)];
        }
#pragma unroll
        for (int i = 0; i < 8; i += 2) {
            int it = items[i + sel];
            int tok = it & 255;
            int bb  = (it >> 8) & 7;
            vreg[i >> 1] = *((const float4*)(evidence + ((size_t)(b0 + bb) * TT + tok) * DD) + sub);
        }
    }

    for (; base < n; base += 64) {
        // store staged gather for this pass
#pragma unroll
        for (int i = 0; i < 8; i += 2)
            *(float4*)(sXw + (i + sel) * DD + sub * 4) = vreg[i >> 1];
        __syncwarp();

        bool cur_valid[8];
#pragma unroll
        for (int i = 0; i < 8; i++) cur_valid[i] = valid[i];

        // issue gather for next pass (latency covered by FMA loop below)
        int next = base + 64;
        if (next < n) {
#pragma unroll
            for (int i = 0; i < 8; i++) {
                int idx = next + i;
                valid[i] = (idx < n);
                items[i] = list[valid[i] ? idx : (n - 1)];
            }
#pragma unroll
            for (int i = 0; i < 8; i += 2) {
                int it = items[i + sel];
                int tok = it & 255;
                int bb  = (it >> 8) & 7;
                vreg[i >> 1] = *((const float4*)(evidence + ((size_t)(b0 + bb) * TT + tok) * DD) + sub);
            }
        }

        u64 acc0[8], acc1[8];
#pragma unroll
        for (int i = 0; i < 8; i++) { acc0[i] = 0ull; acc1[i] = 0ull; }

#pragma unroll
        for (int kq = 0; kq < DD / 4; kq++) {
            ulonglong2 wa = *(const ulonglong2*)(sWq + kq * 256 + 4 * lane);        // feat l, k-quad
            ulonglong2 wb = *(const ulonglong2*)(sWq + kq * 256 + 128 + 4 * lane);  // feat l+32
#pragma unroll
            for (int i = 0; i < 8; i++) {
                ulonglong2 xq = *(const ulonglong2*)(sXw + i * DD + 4 * kq);  // broadcast LDS.128
                acc0[i] = ffma2(xq.x, wa.x, acc0[i]);
                acc0[i] = ffma2(xq.y, wa.y, acc0[i]);
                acc1[i] = ffma2(xq.x, wb.x, acc1[i]);
                acc1[i] = ffma2(xq.y, wb.y, acc1[i]);
            }
        }

#pragma unroll
        for (int i = 0; i < 8; i++) {
            float lo, hi;
            asm("mov.b64 {%0,%1}, %2;" : "=f"(lo), "=f"(hi) : "l"(acc0[i]));
            float h0 = lo + hi + b1a;
            asm("mov.b64 {%0,%1}, %2;" : "=f"(lo), "=f"(hi) : "l"(acc1[i]));
            float h1 = lo + hi + b1b;
            float p = gelu_exact(h0) * w2a + gelu_exact(h1) * w2b;
#pragma unroll
            for (int off = 16; off; off >>= 1)
                p += __shfl_xor_sync(0xffffffffu, p, off);
            if (lane == 0 && cur_valid[i]) {
                gout[base + i] = 1.0f / (1.0f + expf(-(p + b2)));
            }
        }
        __syncwarp();
    }
}

__global__ __launch_bounds__(256, 3)
void cpm_events_kernel(
    const float* __restrict__ evidence,
    const int* __restrict__ marker,
    const int* __restrict__ src_idx,
    const int* __restrict__ src_valid,
    const int* __restrict__ tsym_idx,
    const int* __restrict__ tsym_valid,
    const int* __restrict__ tval_idx,
    const int* __restrict__ tval_valid,
    const int* __restrict__ query_idx,
    const int* __restrict__ query_valid,
    const float* __restrict__ mg_W1, const float* __restrict__ mg_b1,
    const float* __restrict__ mg_W2, const float* __restrict__ mg_b2,
    const float* __restrict__ sg_W1, const float* __restrict__ sg_b1,
    const float* __restrict__ sg_W2, const float* __restrict__ sg_b2,
    int B)
{
    extern __shared__ float sm[];
    float* sW1m  = sm + OFF_W1M;
    float* sW1s  = sm + OFF_W1S;
    float* sb1m  = sm + OFF_B1M;
    float* sw2m  = sm + OFF_W2M;
    float* sb1s  = sm + OFF_B1S;
    float* sw2s  = sm + OFF_W2S;
    int*   sList = (int*)(sm + OFF_LIST);
    float* sGain = sm + OFF_GAIN;
    float* sX    = sm + OFF_X;
    float* sWalk = sm + OFF_WALK;
    float* sNw   = sm + OFF_NW;
    float* sWsum = sm + OFF_WSUM;
    float* sAccv = sm + OFF_ACCV;
    int*   sCnt  = (int*)(sm + OFF_CNT);

    const int tid  = threadIdx.x;
    const int lane = tid & 31;
    const int wid  = tid >> 5;
    const int b0   = blockIdx.x * BPB;

    if (tid < 2) sCnt[tid] = 0;

    // prefetch gate weights into registers (overlap with list build)
    float wrm[16], wrs[16];
#pragma unroll
    for (int i = 0; i < 16; i++) {
        wrm[i] = mg_W1[tid + 256 * i];
        wrs[i] = sg_W1[tid + 256 * i];
    }
    __syncthreads();

    // build merged compact event lists (map from front, step from back)
#pragma unroll
    for (int bi = 0; bi < BPB; bi++) {
        const int b = b0 + bi;
        if (b >= B) break;
        const int gt = b * TT + tid;
        int m  = marker[gt];
        int sv = src_valid[gt];
        if (sv != 0) {
            int si = min(max(src_idx[gt], 0), SS - 1);
            if (m == 1 || m == 2) {
                if (tval_valid[gt] != 0) {
                    int tv = min(max(tval_idx[gt], 0), VV - 1);
                    int p = atomicAdd(&sCnt[0], 1);
                    sList[p] = tid | (bi << 8) | (si << 11) | (tv << 17);
                }
            } else if (m == 3) {
                if (tsym_valid[gt] != 0) {
                    int ts = min(max(tsym_idx[gt], 0), SS - 1);
                    int p = atomicAdd(&sCnt[1], 1);
                    sList[LCAP - 1 - p] = tid | (bi << 8) | (si << 11) | (ts << 17);
                }
            }
        }
    }

    // store prefetched weights, k-quad interleaved
#pragma unroll
    for (int i = 0; i < 16; i++) {
        int idx = tid + 256 * i;
        int k = idx >> 6, f = idx & 63;
        int dst = (k >> 2) * 256 + (f << 2) + (k & 3);
        sW1m[dst] = wrm[i];
        sW1s[dst] = wrs[i];
    }
    if (tid < DD) {
        sb1m[tid] = mg_b1[tid]; sw2m[tid] = mg_W2[tid];
        sb1s[tid] = sg_b1[tid]; sw2s[tid] = sg_W2[tid];
    }
    __syncthreads();

    const int nmap  = sCnt[0];
    const int nstep = sCnt[1];
    const int*   lstep = sList + LCAP - nstep;   // ascending, scrambled order (ok)
    float*       gstep = sGain + LCAP - nstep;
    float* sXw = sX + wid * 8 * DD;

    process_events8(sList, nmap, mg_b2[0], sGain, sW1m, sb1m, sw2m,
                    evidence, b0, sXw, lane);
    process_events8(lstep, nstep, sg_b2[0], gstep, sW1s, sb1s, sw2s,
                    evidence, b0, sXw, lane);
    __syncthreads();

    // ---- sparse walk: warp bi -> batch bi ----
    {
        const int bi = wid;
        const int b = b0 + bi;
        if (b < B) {
            float* walk = sWalk + bi * SS;
            float* nw   = sNw   + bi * SS;
            float* wsum = sWsum + bi * SS;
            float* accv = sAccv + bi * VV;

            int q = min(max(query_idx[b], 0), SS - 1);
            float qv = (float)query_valid[b];
#pragma unroll
            for (int i = lane; i < SS; i += 32) {
                float w = (i == q) ? qv : 0.f;
                walk[i] = w; wsum[i] = w;
            }
            if (lane < VV) accv[lane] = 0.f;
            __syncwarp();

            for (int it = 0; it < 3; it++) {
#pragma unroll
                for (int i = lane; i < SS; i += 32) nw[i] = 0.f;
                __syncwarp();
                for (int e = lane; e < nstep; e += 32) {
                    int item = lstep[e];
                    if (((item >> 8) & 7) == bi) {
                        int src = (item >> 11) & 63;
                        int tgt = (item >> 17) & 63;
                        atomicAdd(&nw[tgt], gstep[e] * walk[src]);
                    }
                }
                __syncwarp();
#pragma unroll
                for (int i = lane; i < SS; i += 32) {
                    float w = nw[i];
                    walk[i] = w; wsum[i] += w;
                }
                __syncwarp();
            }
            for (int e = lane; e < nmap; e += 32) {
                int item = sList[e];
                if (((item >> 8) & 7) == bi) {
                    int src = (item >> 11) & 63;
                    int tv  = (item >> 17) & 63;
                    atomicAdd(&accv[tv], sGain[e] * wsum[src]);
                }
            }
        }
    }
    __syncthreads();

    // write per-batch state to scratch
    for (int idx = tid; idx < BPB * 96; idx += 256) {
        int bi = idx / 96, j = idx - bi * 96;
        int b = b0 + bi;
        if (b < B) {
            float v = (j < 64) ? sWsum[bi * SS + j] : sAccv[bi * VV + (j - 64)];
            g_scratch[(size_t)b * 96 + j] = v;
        }
    }
}

// ---------------- kernel 2: graph_state + heads (register-weight GEMM) ----------------
// transposed state arrays, 4 batches per block, row stride 4
#define RS2 4
#define K2_WS    0                       // 96*4  = 384
#define K2_GS    (K2_WS + 96 * RS2)      // 128*4 = 512
#define K2_H     (K2_GS + 128 * RS2)     // 128*4 = 512
#define SMEM2_FLOATS (K2_H + 128 * RS2)

__global__ __launch_bounds__(256)
void cpm_heads_kernel(
    const float* __restrict__ symbol_emb,
    const float* __restrict__ value_emb,
    const float* __restrict__ sf_W1, const float* __restrict__ sf_b1,
    const float* __restrict__ sf_W2, const float* __restrict__ sf_b2,
    const float* __restrict__ oh_W1, const float* __restrict__ oh_b1,
    const float* __restrict__ oh_W2, const float* __restrict__ oh_b2,
    float* __restrict__ out, int B)
{
    extern __shared__ float sm[];
    const int tid = threadIdx.x;
    const int b0  = blockIdx.x * K2B;

    // stage per-batch states, transposed: ws_T[j][bi]
    for (int i = tid; i < K2B * 96; i += 256) {
        int bi = i / 96, j = i - bi * 96;
        int b = b0 + bi;
        sm[K2_WS + j * RS2 + bi] = (b < B) ? g_scratch[(size_t)b * 96 + j] : 0.f;
    }
    __syncthreads();

    const int col  = tid & 127;
    const int half = tid >> 7;          // 2 batches per half
    const int boff = half * 2;

    // ---- phase A: gs_T[col][bi] ----
    {
        u64 acc = 0ull;
        if (col < DD) {
#pragma unroll 8
            for (int s = 0; s < SS; s++) {
                u64 wd = packdup(__ldg(symbol_emb + s * DD + col));
                acc = ffma2(*(const u64*)(sm + K2_WS + s * RS2 + boff), wd, acc);
            }
        } else {
            const int d = col - DD;
#pragma unroll 8
            for (int v = 0; v < VV; v++) {
                u64 wd = packdup(__ldg(value_emb + v * DD + d));
                acc = ffma2(*(const u64*)(sm + K2_WS + (64 + v) * RS2 + boff), wd, acc);
            }
        }
        *(u64*)(sm + K2_GS + col * RS2 + boff) = acc;
    }
    __syncthreads();

    // ---- phase B: h_T[col][bi] = gelu(bias + gs @ W1) ----
    {
        u64 acc = 0ull;
        const float* W1 = (col < DD) ? (oh_W1 + col) : (sf_W1 + col - DD);
#pragma unroll 8
        for (int k = 0; k < 2 * DD; k++) {
            u64 wd = packdup(__ldg(W1 + k * DD));
            acc = ffma2(*(const u64*)(sm + K2_GS + k * RS2 + boff), wd, acc);
        }
        float bias = (col < DD) ? oh_b1[col] : sf_b1[col - DD];
        float lo, hi;
        asm("mov.b64 {%0,%1}, %2;" : "=f"(lo), "=f"(hi) : "l"(acc));
        float* hrow = sm + K2_H + col * RS2 + boff;
        hrow[0] = gelu_exact(lo + bias);
        hrow[1] = gelu_exact(hi + bias);
    }
    __syncthreads();

    // ---- phase C: outputs (col < 96 per half) ----
    if (col < 96) {
        const int j = col;
        u64 acc = 0ull;
        if (j < VV) {
#pragma unroll 8
            for (int k = 0; k < DD; k++) {
                u64 wd = packdup(__ldg(oh_W2 + k * VV + j));
                acc = ffma2(*(const u64*)(sm + K2_H + k * RS2 + boff), wd, acc);
            }
            float bias = oh_b2[j];
            float lo, hi;
            asm("mov.b64 {%0,%1}, %2;" : "=f"(lo), "=f"(hi) : "l"(acc));
            int b = b0 + boff;
            if (b < B)     out[(size_t)b * VV + j] = lo + bias;
            if (b + 1 < B) out[(size_t)(b + 1) * VV + j] = hi + bias;
        } else {
            const int d = j - VV;
#pragma unroll 8
            for (int k = 0; k < DD; k++) {
                u64 wd = packdup(__ldg(sf_W2 + k * DD + d));
                acc = ffma2(*(const u64*)(sm + K2_H + (64 + k) * RS2 + boff), wd, acc);
            }
            float bias = sf_b2[d];
            float lo, hi;
            asm("mov.b64 {%0,%1}, %2;" : "=f"(lo), "=f"(hi) : "l"(acc));
            float* fb = out + (size_t)B * VV;
            int b = b0 + boff;
            if (b < B)     fb[(size_t)b * DD + d] = lo + bias;
            if (b + 1 < B) fb[(size_t)(b + 1) * DD + d] = hi + bias;
        }
    }
}

extern "C" void kernel_launch(void* const* d_in, const int* in_sizes, int n_in,
                              void* d_out, int out_size)
{
    const float* evidence    = (const float*)d_in[0];
    const int*   marker      = (const int*)d_in[1];
    const int*   src_idx     = (const int*)d_in[2];
    const int*   src_valid   = (const int*)d_in[3];
    const int*   tsym_idx    = (const int*)d_in[4];
    const int*   tsym_valid  = (const int*)d_in[5];
    const int*   tval_idx    = (const int*)d_in[6];
    const int*   tval_valid  = (const int*)d_in[7];
    const int*   query_idx   = (const int*)d_in[8];
    const int*   query_valid = (const int*)d_in[9];
    const float* symbol_emb  = (const float*)d_in[10];
    const float* value_emb   = (const float*)d_in[11];
    const float* mg_W1 = (const float*)d_in[12];
    const float* mg_b1 = (const float*)d_in[13];
    const float* mg_W2 = (const float*)d_in[14];
    const float* mg_b2 = (const float*)d_in[15];
    const float* sg_W1 = (const float*)d_in[16];
    const float* sg_b1 = (const float*)d_in[17];
    const float* sg_W2 = (const float*)d_in[18];
    const float* sg_b2 = (const float*)d_in[19];
    const float* sf_W1 = (const float*)d_in[20];
    const float* sf_b1 = (const float*)d_in[21];
    const float* sf_W2 = (const float*)d_in[22];
    const float* sf_b2 = (const float*)d_in[23];
    const float* oh_W1 = (const float*)d_in[24];
    const float* oh_b1 = (const float*)d_in[25];
    const float* oh_W2 = (const float*)d_in[26];
    const float* oh_b2 = (const float*)d_in[27];

    const int B = in_sizes[8];

    const int smem1 = SMEM1_FLOATS * (int)sizeof(float);
    const int smem2 = SMEM2_FLOATS * (int)sizeof(float);
    cudaFuncSetAttribute(cpm_events_kernel, cudaFuncAttributeMaxDynamicSharedMemorySize, smem1);
    cudaFuncSetAttribute(cpm_heads_kernel,  cudaFuncAttributeMaxDynamicSharedMemorySize, smem2);

    const int grid1 = (B + BPB - 1) / BPB;
    cpm_events_kernel<<<grid1, 256, smem1>>>(
        evidence, marker, src_idx, src_valid, tsym_idx, tsym_valid,
        tval_idx, tval_valid, query_idx, query_valid,
        mg_W1, mg_b1, mg_W2, mg_b2,
        sg_W1, sg_b1, sg_W2, sg_b2, B);

    const int grid2 = (B + K2B - 1) / K2B;
    cpm_heads_kernel<<<grid2, 256, smem2>>>(
        symbol_emb, value_emb,
        sf_W1, sf_b1, sf_W2, sf_b2,
        oh_W1, oh_b1, oh_W2, oh_b2,
        (float*)d_out, B);
}

// round 10
// speedup vs baseline: 1.1354x; 1.1354x over previous
#include <cuda_runtime.h>
#include <math.h>

#define TT 256
#define DD 64
#define SS 64
#define VV 32
#define BPB 8            // batches per block (kernel 1)
#define K2B 4            // batches per block (kernel 2)
#define LCAP 2048        // shared list capacity (map front, step back)

typedef unsigned long long u64;

// per-batch intermediate: [0:64) wsum, [64:96) accv
__device__ float g_scratch[4096 * 96];

// ---------------- kernel 1 shared layout (floats) ----------------
#define OFF_W1M   0        // 4096 quad-interleaved
#define OFF_W1S   4096     // 4096
#define OFF_B1M   8192     // 64
#define OFF_W2M   8256     // 64
#define OFF_B1S   8320     // 64
#define OFF_W2S   8384     // 64
#define OFF_LIST  8448     // 2048 ints shared (map front / step back)
#define OFF_GAIN  10496    // 2048 floats shared (aligned with LIST)
#define OFF_X     12544    // 8 warps * 8 tok * 64 = 4096
#define OFF_WALK  16640    // 8*64
#define OFF_NW    17152    // 8*64
#define OFF_WSUM  17664    // 8*64
#define OFF_ACCV  18176    // 8*32
#define OFF_CNT   18432    // 2 ints
#define SMEM1_FLOATS 18436

__device__ __forceinline__ float gelu_exact(float x) {
    return 0.5f * x * (1.0f + erff(x * 0.70710678118654752440f));
}

__device__ __forceinline__ u64 ffma2(u64 a, u64 b, u64 c) {
    u64 d;
    asm("fma.rn.f32x2 %0, %1, %2, %3;" : "=l"(d) : "l"(a), "l"(b), "l"(c));
    return d;
}
__device__ __forceinline__ u64 packdup(float x) {
    u64 d;
    asm("mov.b64 %0, {%1, %1};" : "=l"(d) : "f"(x));
    return d;
}

// warp-cooperative gate MLP, 8 tokens/pass (no pipelining: lean registers).
// Quad weight layout: Wq[kq*256 + f*4 + j] = W[4kq+j][f]
// lane l owns features l and l+32; acc u64 = (even-k partial, odd-k partial)
// item: tok[0:8) | bi[8:11) | src[11:17) | tgt[17:23)
__device__ __forceinline__ void process_events8(
    const int* __restrict__ list, int n, float b2,
    float* __restrict__ gout,
    const float* __restrict__ sWq, const float* __restrict__ sb1,
    const float* __restrict__ sw2,
    const float* __restrict__ evidence, int b0,
    float* __restrict__ sXw, int lane)
{
    const int wid = threadIdx.x >> 5;
    const int sel = lane >> 4;           // 0: even token of pair, 1: odd
    const int sub = lane & 15;           // 16B chunk within row

    const float b1a = sb1[lane], b1b = sb1[lane + 32];
    const float w2a = sw2[lane], w2b = sw2[lane + 32];

    for (int base = wid * 8; base < n; base += 64) {
        int items[8];
        bool valid[8];
#pragma unroll
        for (int i = 0; i < 8; i++) {
            int idx = base + i;
            valid[i] = (idx < n);
            items[i] = list[valid[i] ? idx : (n - 1)];
        }
        // gather 8 evidence rows, 2 tokens per LDG.128 (half-warp each)
#pragma unroll
        for (int i = 0; i < 8; i += 2) {
            int it = items[i + sel];
            int tok = it & 255;
            int bb  = (it >> 8) & 7;
            float4 v = *((const float4*)(evidence + ((size_t)(b0 + bb) * TT + tok) * DD) + sub);
            *(float4*)(sXw + (i + sel) * DD + sub * 4) = v;
        }
        __syncwarp();

        u64 acc0[8], acc1[8];
#pragma unroll
        for (int i = 0; i < 8; i++) { acc0[i] = 0ull; acc1[i] = 0ull; }

#pragma unroll
        for (int kq = 0; kq < DD / 4; kq++) {
            ulonglong2 wa = *(const ulonglong2*)(sWq + kq * 256 + 4 * lane);        // feat l, k-quad
            ulonglong2 wb = *(const ulonglong2*)(sWq + kq * 256 + 128 + 4 * lane);  // feat l+32
#pragma unroll
            for (int i = 0; i < 8; i++) {
                ulonglong2 xq = *(const ulonglong2*)(sXw + i * DD + 4 * kq);  // broadcast LDS.128
                acc0[i] = ffma2(xq.x, wa.x, acc0[i]);
                acc0[i] = ffma2(xq.y, wa.y, acc0[i]);
                acc1[i] = ffma2(xq.x, wb.x, acc1[i]);
                acc1[i] = ffma2(xq.y, wb.y, acc1[i]);
            }
        }

#pragma unroll
        for (int i = 0; i < 8; i++) {
            float lo, hi;
            asm("mov.b64 {%0,%1}, %2;" : "=f"(lo), "=f"(hi) : "l"(acc0[i]));
            float h0 = lo + hi + b1a;
            asm("mov.b64 {%0,%1}, %2;" : "=f"(lo), "=f"(hi) : "l"(acc1[i]));
            float h1 = lo + hi + b1b;
            float p = gelu_exact(h0) * w2a + gelu_exact(h1) * w2b;
#pragma unroll
            for (int off = 16; off; off >>= 1)
                p += __shfl_xor_sync(0xffffffffu, p, off);
            if (lane == 0 && valid[i]) {
                gout[base + i] = 1.0f / (1.0f + expf(-(p + b2)));
            }
        }
        __syncwarp();
    }
}

__global__ __launch_bounds__(256, 3)
void cpm_events_kernel(
    const float* __restrict__ evidence,
    const int* __restrict__ marker,
    const int* __restrict__ src_idx,
    const int* __restrict__ src_valid,
    const int* __restrict__ tsym_idx,
    const int* __restrict__ tsym_valid,
    const int* __restrict__ tval_idx,
    const int* __restrict__ tval_valid,
    const int* __restrict__ query_idx,
    const int* __restrict__ query_valid,
    const float* __restrict__ mg_W1, const float* __restrict__ mg_b1,
    const float* __restrict__ mg_W2, const float* __restrict__ mg_b2,
    const float* __restrict__ sg_W1, const float* __restrict__ sg_b1,
    const float* __restrict__ sg_W2, const float* __restrict__ sg_b2,
    int B)
{
    extern __shared__ float sm[];
    float* sW1m  = sm + OFF_W1M;
    float* sW1s  = sm + OFF_W1S;
    float* sb1m  = sm + OFF_B1M;
    float* sw2m  = sm + OFF_W2M;
    float* sb1s  = sm + OFF_B1S;
    float* sw2s  = sm + OFF_W2S;
    int*   sList = (int*)(sm + OFF_LIST);
    float* sGain = sm + OFF_GAIN;
    float* sX    = sm + OFF_X;
    float* sWalk = sm + OFF_WALK;
    float* sNw   = sm + OFF_NW;
    float* sWsum = sm + OFF_WSUM;
    float* sAccv = sm + OFF_ACCV;
    int*   sCnt  = (int*)(sm + OFF_CNT);

    const int tid  = threadIdx.x;
    const int lane = tid & 31;
    const int wid  = tid >> 5;
    const int b0   = blockIdx.x * BPB;

    if (tid < 2) sCnt[tid] = 0;
    __syncthreads();

    // build merged compact event lists (map from front, step from back)
#pragma unroll
    for (int bi = 0; bi < BPB; bi++) {
        const int b = b0 + bi;
        if (b >= B) break;
        const int gt = b * TT + tid;
        int m  = marker[gt];
        int sv = src_valid[gt];
        if (sv != 0) {
            int si = min(max(src_idx[gt], 0), SS - 1);
            if (m == 1 || m == 2) {
                if (tval_valid[gt] != 0) {
                    int tv = min(max(tval_idx[gt], 0), VV - 1);
                    int p = atomicAdd(&sCnt[0], 1);
                    sList[p] = tid | (bi << 8) | (si << 11) | (tv << 17);
                }
            } else if (m == 3) {
                if (tsym_valid[gt] != 0) {
                    int ts = min(max(tsym_idx[gt], 0), SS - 1);
                    int p = atomicAdd(&sCnt[1], 1);
                    sList[LCAP - 1 - p] = tid | (bi << 8) | (si << 11) | (ts << 17);
                }
            }
        }
    }

    // stage gate weights, k-quad interleaved (plain LDG->STS)
    for (int i = tid; i < DD * DD; i += 256) {
        int k = i >> 6, f = i & 63;
        int dst = (k >> 2) * 256 + (f << 2) + (k & 3);
        sW1m[dst] = mg_W1[i];
        sW1s[dst] = sg_W1[i];
    }
    if (tid < DD) {
        sb1m[tid] = mg_b1[tid]; sw2m[tid] = mg_W2[tid];
        sb1s[tid] = sg_b1[tid]; sw2s[tid] = sg_W2[tid];
    }
    __syncthreads();

    const int nmap  = sCnt[0];
    const int nstep = sCnt[1];
    const int*   lstep = sList + LCAP - nstep;   // ascending, scrambled order (ok)
    float*       gstep = sGain + LCAP - nstep;
    float* sXw = sX + wid * 8 * DD;

    process_events8(sList, nmap, mg_b2[0], sGain, sW1m, sb1m, sw2m,
                    evidence, b0, sXw, lane);
    process_events8(lstep, nstep, sg_b2[0], gstep, sW1s, sb1s, sw2s,
                    evidence, b0, sXw, lane);
    __syncthreads();

    // ---- sparse walk: warp bi -> batch bi ----
    {
        const int bi = wid;
        const int b = b0 + bi;
        if (b < B) {
            float* walk = sWalk + bi * SS;
            float* nw   = sNw   + bi * SS;
            float* wsum = sWsum + bi * SS;
            float* accv = sAccv + bi * VV;

            int q = min(max(query_idx[b], 0), SS - 1);
            float qv = (float)query_valid[b];
#pragma unroll
            for (int i = lane; i < SS; i += 32) {
                float w = (i == q) ? qv : 0.f;
                walk[i] = w; wsum[i] = w;
            }
            if (lane < VV) accv[lane] = 0.f;
            __syncwarp();

            for (int it = 0; it < 3; it++) {
#pragma unroll
                for (int i = lane; i < SS; i += 32) nw[i] = 0.f;
                __syncwarp();
                for (int e = lane; e < nstep; e += 32) {
                    int item = lstep[e];
                    if (((item >> 8) & 7) == bi) {
                        int src = (item >> 11) & 63;
                        int tgt = (item >> 17) & 63;
                        atomicAdd(&nw[tgt], gstep[e] * walk[src]);
                    }
                }
                __syncwarp();
#pragma unroll
                for (int i = lane; i < SS; i += 32) {
                    float w = nw[i];
                    walk[i] = w; wsum[i] += w;
                }
                __syncwarp();
            }
            for (int e = lane; e < nmap; e += 32) {
                int item = sList[e];
                if (((item >> 8) & 7) == bi) {
                    int src = (item >> 11) & 63;
                    int tv  = (item >> 17) & 63;
                    atomicAdd(&accv[tv], sGain[e] * wsum[src]);
                }
            }
        }
    }
    __syncthreads();

    // write per-batch state to scratch
    for (int idx = tid; idx < BPB * 96; idx += 256) {
        int bi = idx / 96, j = idx - bi * 96;
        int b = b0 + bi;
        if (b < B) {
            float v = (j < 64) ? sWsum[bi * SS + j] : sAccv[bi * VV + (j - 64)];
            g_scratch[(size_t)b * 96 + j] = v;
        }
    }
}

// ---------------- kernel 2: graph_state + heads (register-weight GEMM) ----------------
// transposed state arrays, 4 batches per block, row stride 4
#define RS2 4
#define K2_WS    0                       // 96*4  = 384
#define K2_GS    (K2_WS + 96 * RS2)      // 128*4 = 512
#define K2_H     (K2_GS + 128 * RS2)     // 128*4 = 512
#define SMEM2_FLOATS (K2_H + 128 * RS2)

__global__ __launch_bounds__(256)
void cpm_heads_kernel(
    const float* __restrict__ symbol_emb,
    const float* __restrict__ value_emb,
    const float* __restrict__ sf_W1, const float* __restrict__ sf_b1,
    const float* __restrict__ sf_W2, const float* __restrict__ sf_b2,
    const float* __restrict__ oh_W1, const float* __restrict__ oh_b1,
    const float* __restrict__ oh_W2, const float* __restrict__ oh_b2,
    float* __restrict__ out, int B)
{
    extern __shared__ float sm[];
    const int tid = threadIdx.x;
    const int b0  = blockIdx.x * K2B;

    // stage per-batch states, transposed: ws_T[j][bi]
    for (int i = tid; i < K2B * 96; i += 256) {
        int bi = i / 96, j = i - bi * 96;
        int b = b0 + bi;
        sm[K2_WS + j * RS2 + bi] = (b < B) ? g_scratch[(size_t)b * 96 + j] : 0.f;
    }
    __syncthreads();

    const int col  = tid & 127;
    const int half = tid >> 7;          // 2 batches per half
    const int boff = half * 2;

    // ---- phase A: gs_T[col][bi] ----
    {
        u64 acc = 0ull;
        if (col < DD) {
#pragma unroll 8
            for (int s = 0; s < SS; s++) {
                u64 wd = packdup(__ldg(symbol_emb + s * DD + col));
                acc = ffma2(*(const u64*)(sm + K2_WS + s * RS2 + boff), wd, acc);
            }
        } else {
            const int d = col - DD;
#pragma unroll 8
            for (int v = 0; v < VV; v++) {
                u64 wd = packdup(__ldg(value_emb + v * DD + d));
                acc = ffma2(*(const u64*)(sm + K2_WS + (64 + v) * RS2 + boff), wd, acc);
            }
        }
        *(u64*)(sm + K2_GS + col * RS2 + boff) = acc;
    }
    __syncthreads();

    // ---- phase B: h_T[col][bi] = gelu(bias + gs @ W1) ----
    {
        u64 acc = 0ull;
        const float* W1 = (col < DD) ? (oh_W1 + col) : (sf_W1 + col - DD);
#pragma unroll 8
        for (int k = 0; k < 2 * DD; k++) {
            u64 wd = packdup(__ldg(W1 + k * DD));
            acc = ffma2(*(const u64*)(sm + K2_GS + k * RS2 + boff), wd, acc);
        }
        float bias = (col < DD) ? oh_b1[col] : sf_b1[col - DD];
        float lo, hi;
        asm("mov.b64 {%0,%1}, %2;" : "=f"(lo), "=f"(hi) : "l"(acc));
        float* hrow = sm + K2_H + col * RS2 + boff;
        hrow[0] = gelu_exact(lo + bias);
        hrow[1] = gelu_exact(hi + bias);
    }
    __syncthreads();

    // ---- phase C: outputs (col < 96 per half) ----
    if (col < 96) {
        const int j = col;
        u64 acc = 0ull;
        if (j < VV) {
#pragma unroll 8
            for (int k = 0; k < DD; k++) {
                u64 wd = packdup(__ldg(oh_W2 + k * VV + j));
                acc = ffma2(*(const u64*)(sm + K2_H + k * RS2 + boff), wd, acc);
            }
            float bias = oh_b2[j];
            float lo, hi;
            asm("mov.b64 {%0,%1}, %2;" : "=f"(lo), "=f"(hi) : "l"(acc));
            int b = b0 + boff;
            if (b < B)     out[(size_t)b * VV + j] = lo + bias;
            if (b + 1 < B) out[(size_t)(b + 1) * VV + j] = hi + bias;
        } else {
            const int d = j - VV;
#pragma unroll 8
            for (int k = 0; k < DD; k++) {
                u64 wd = packdup(__ldg(sf_W2 + k * DD + d));
                acc = ffma2(*(const u64*)(sm + K2_H + (64 + k) * RS2 + boff), wd, acc);
            }
            float bias = sf_b2[d];
            float lo, hi;
            asm("mov.b64 {%0,%1}, %2;" : "=f"(lo), "=f"(hi) : "l"(acc));
            float* fb = out + (size_t)B * VV;
            int b = b0 + boff;
            if (b < B)     fb[(size_t)b * DD + d] = lo + bias;
            if (b + 1 < B) fb[(size_t)(b + 1) * DD + d] = hi + bias;
        }
    }
}

extern "C" void kernel_launch(void* const* d_in, const int* in_sizes, int n_in,
                              void* d_out, int out_size)
{
    const float* evidence    = (const float*)d_in[0];
    const int*   marker      = (const int*)d_in[1];
    const int*   src_idx     = (const int*)d_in[2];
    const int*   src_valid   = (const int*)d_in[3];
    const int*   tsym_idx    = (const int*)d_in[4];
    const int*   tsym_valid  = (const int*)d_in[5];
    const int*   tval_idx    = (const int*)d_in[6];
    const int*   tval_valid  = (const int*)d_in[7];
    const int*   query_idx   = (const int*)d_in[8];
    const int*   query_valid = (const int*)d_in[9];
    const float* symbol_emb  = (const float*)d_in[10];
    const float* value_emb   = (const float*)d_in[11];
    const float* mg_W1 = (const float*)d_in[12];
    const float* mg_b1 = (const float*)d_in[13];
    const float* mg_W2 = (const float*)d_in[14];
    const float* mg_b2 = (const float*)d_in[15];
    const float* sg_W1 = (const float*)d_in[16];
    const float* sg_b1 = (const float*)d_in[17];
    const float* sg_W2 = (const float*)d_in[18];
    const float* sg_b2 = (const float*)d_in[19];
    const float* sf_W1 = (const float*)d_in[20];
    const float* sf_b1 = (const float*)d_in[21];
    const float* sf_W2 = (const float*)d_in[22];
    const float* sf_b2 = (const float*)d_in[23];
    const float* oh_W1 = (const float*)d_in[24];
    const float* oh_b1 = (const float*)d_in[25];
    const float* oh_W2 = (const float*)d_in[26];
    const float* oh_b2 = (const float*)d_in[27];

    const int B = in_sizes[8];

    const int smem1 = SMEM1_FLOATS * (int)sizeof(float);
    const int smem2 = SMEM2_FLOATS * (int)sizeof(float);
    cudaFuncSetAttribute(cpm_events_kernel, cudaFuncAttributeMaxDynamicSharedMemorySize, smem1);
    cudaFuncSetAttribute(cpm_heads_kernel,  cudaFuncAttributeMaxDynamicSharedMemorySize, smem2);

    const int grid1 = (B + BPB - 1) / BPB;
    cpm_events_kernel<<<grid1, 256, smem1>>>(
        evidence, marker, src_idx, src_valid, tsym_idx, tsym_valid,
        tval_idx, tval_valid, query_idx, query_valid,
        mg_W1, mg_b1, mg_W2, mg_b2,
        sg_W1, sg_b1, sg_W2, sg_b2, B);

    const int grid2 = (B + K2B - 1) / K2B;
    cpm_heads_kernel<<<grid2, 256, smem2>>>(
        symbol_emb, value_emb,
        sf_W1, sf_b1, sf_W2, sf_b2,
        oh_W1, oh_b1, oh_W2, oh_b2,
        (float*)d_out, B);
}

// round 11
// speedup vs baseline: 1.3203x; 1.1629x over previous
#include <cuda_runtime.h>
#include <math.h>

#define TT 256
#define DD 64
#define SS 64
#define VV 32
#define BPB 8            // batches per block

typedef unsigned long long u64;

// ---------------- shared layout (floats) ----------------
#define OFF_W1M   0        // 4096 quad-interleaved
#define OFF_W1S   4096     // 4096
#define OFF_B1M   8192     // 64
#define OFF_W2M   8256     // 64
#define OFF_B1S   8320     // 64
#define OFF_W2S   8384     // 64
#define OFF_LMAP  8448     // 2048 ints
#define OFF_LSTEP 10496    // 2048 ints
#define OFF_GMAP  12544    // 2048
#define OFF_GSTEP 14592    // 2048
#define OFF_X     16640    // 8 warps * 8 tok * 64 = 4096 (reused by head phases)
#define OFF_WALK  20736    // 8*64
#define OFF_NW    21248    // 8*64
#define OFF_WSUM  21760    // 8*64
#define OFF_ACCV  22272    // 8*32
#define OFF_CNT   22528    // 2 ints
#define SMEM1_FLOATS 22532

// head-phase reuse of sX region (2816 <= 4096 floats)
#define HT_WS 0            // 96*8
#define HT_GS 768          // 128*8
#define HT_H  1792         // 128*8

__device__ __forceinline__ float gelu_exact(float x) {
    return 0.5f * x * (1.0f + erff(x * 0.70710678118654752440f));
}

__device__ __forceinline__ u64 ffma2(u64 a, u64 b, u64 c) {
    u64 d;
    asm("fma.rn.f32x2 %0, %1, %2, %3;" : "=l"(d) : "l"(a), "l"(b), "l"(c));
    return d;
}
__device__ __forceinline__ u64 packdup(float x) {
    u64 d;
    asm("mov.b64 %0, {%1, %1};" : "=l"(d) : "f"(x));
    return d;
}

// warp-cooperative gate MLP, 8 tokens/pass, gather pipelined one pass ahead.
// Quad weight layout: Wq[kq*256 + f*4 + j] = W[4kq+j][f]
// item: tok[0:8) | bi[8:11) | src[11:17) | tgt[17:23)
__device__ __forceinline__ void process_events8(
    const int* __restrict__ list, int n, float b2,
    float* __restrict__ gout,
    const float* __restrict__ sWq, const float* __restrict__ sb1,
    const float* __restrict__ sw2,
    const float* __restrict__ evidence, int b0,
    float* __restrict__ sXw, int lane)
{
    const int wid = threadIdx.x >> 5;
    const int sel = lane >> 4;           // 0: even token of pair, 1: odd
    const int sub = lane & 15;           // 16B chunk within row

    int items[8];
    bool valid[8];
    float4 vreg[4];

    int base = wid * 8;
    if (base < n) {
#pragma unroll
        for (int i = 0; i < 8; i++) {
            int idx = base + i;
            valid[i] = (idx < n);
            items[i] = list[valid[i] ? idx : (n - 1)];
        }
#pragma unroll
        for (int i = 0; i < 8; i += 2) {
            int it = items[i + sel];
            int tok = it & 255;
            int bb  = (it >> 8) & 7;
            vreg[i >> 1] = *((const float4*)(evidence + ((size_t)(b0 + bb) * TT + tok) * DD) + sub);
        }
    }

    for (; base < n; base += 64) {
        // store staged gather for this pass
#pragma unroll
        for (int i = 0; i < 8; i += 2)
            *(float4*)(sXw + (i + sel) * DD + sub * 4) = vreg[i >> 1];
        __syncwarp();

        bool cur_valid[8];
#pragma unroll
        for (int i = 0; i < 8; i++) cur_valid[i] = valid[i];

        // issue gather for next pass (latency covered by FMA loop below)
        int next = base + 64;
        if (next < n) {
#pragma unroll
            for (int i = 0; i < 8; i++) {
                int idx = next + i;
                valid[i] = (idx < n);
                items[i] = list[valid[i] ? idx : (n - 1)];
            }
#pragma unroll
            for (int i = 0; i < 8; i += 2) {
                int it = items[i + sel];
                int tok = it & 255;
                int bb  = (it >> 8) & 7;
                vreg[i >> 1] = *((const float4*)(evidence + ((size_t)(b0 + bb) * TT + tok) * DD) + sub);
            }
        }

        u64 acc0[8], acc1[8];
#pragma unroll
        for (int i = 0; i < 8; i++) { acc0[i] = 0ull; acc1[i] = 0ull; }

#pragma unroll
        for (int kq = 0; kq < DD / 4; kq++) {
            ulonglong2 wa = *(const ulonglong2*)(sWq + kq * 256 + 4 * lane);        // feat l, k-quad
            ulonglong2 wb = *(const ulonglong2*)(sWq + kq * 256 + 128 + 4 * lane);  // feat l+32
#pragma unroll
            for (int i = 0; i < 8; i++) {
                ulonglong2 xq = *(const ulonglong2*)(sXw + i * DD + 4 * kq);  // broadcast LDS.128
                acc0[i] = ffma2(xq.x, wa.x, acc0[i]);
                acc0[i] = ffma2(xq.y, wa.y, acc0[i]);
                acc1[i] = ffma2(xq.x, wb.x, acc1[i]);
                acc1[i] = ffma2(xq.y, wb.y, acc1[i]);
            }
        }

        float b1a = sb1[lane], b1b = sb1[lane + 32];
        float w2a = sw2[lane], w2b = sw2[lane + 32];
#pragma unroll
        for (int i = 0; i < 8; i++) {
            float lo, hi;
            asm("mov.b64 {%0,%1}, %2;" : "=f"(lo), "=f"(hi) : "l"(acc0[i]));
            float h0 = lo + hi + b1a;
            asm("mov.b64 {%0,%1}, %2;" : "=f"(lo), "=f"(hi) : "l"(acc1[i]));
            float h1 = lo + hi + b1b;
            float p = gelu_exact(h0) * w2a + gelu_exact(h1) * w2b;
#pragma unroll
            for (int off = 16; off; off >>= 1)
                p += __shfl_xor_sync(0xffffffffu, p, off);
            if (lane == 0 && cur_valid[i]) {
                gout[base + i] = 1.0f / (1.0f + expf(-(p + b2)));
            }
        }
        __syncwarp();
    }
}

__global__ __launch_bounds__(256, 2)
void cpm_fused_kernel(
    const float* __restrict__ evidence,
    const int* __restrict__ marker,
    const int* __restrict__ src_idx,
    const int* __restrict__ src_valid,
    const int* __restrict__ tsym_idx,
    const int* __restrict__ tsym_valid,
    const int* __restrict__ tval_idx,
    const int* __restrict__ tval_valid,
    const int* __restrict__ query_idx,
    const int* __restrict__ query_valid,
    const float* __restrict__ symbol_emb,
    const float* __restrict__ value_emb,
    const float* __restrict__ mg_W1, const float* __restrict__ mg_b1,
    const float* __restrict__ mg_W2, const float* __restrict__ mg_b2,
    const float* __restrict__ sg_W1, const float* __restrict__ sg_b1,
    const float* __restrict__ sg_W2, const float* __restrict__ sg_b2,
    const float* __restrict__ sf_W1, const float* __restrict__ sf_b1,
    const float* __restrict__ sf_W2, const float* __restrict__ sf_b2,
    const float* __restrict__ oh_W1, const float* __restrict__ oh_b1,
    const float* __restrict__ oh_W2, const float* __restrict__ oh_b2,
    float* __restrict__ out, int B)
{
    extern __shared__ float sm[];
    float* sW1m  = sm + OFF_W1M;
    float* sW1s  = sm + OFF_W1S;
    float* sb1m  = sm + OFF_B1M;
    float* sw2m  = sm + OFF_W2M;
    float* sb1s  = sm + OFF_B1S;
    float* sw2s  = sm + OFF_W2S;
    int*   sLmap = (int*)(sm + OFF_LMAP);
    int*   sLstep= (int*)(sm + OFF_LSTEP);
    float* sGmap = sm + OFF_GMAP;
    float* sGstep= sm + OFF_GSTEP;
    float* sX    = sm + OFF_X;
    float* sWalk = sm + OFF_WALK;
    float* sNw   = sm + OFF_NW;
    float* sWsum = sm + OFF_WSUM;
    float* sAccv = sm + OFF_ACCV;
    int*   sCnt  = (int*)(sm + OFF_CNT);

    const int tid  = threadIdx.x;
    const int lane = tid & 31;
    const int wid  = tid >> 5;
    const int b0   = blockIdx.x * BPB;

    if (tid < 2) sCnt[tid] = 0;

    // prefetch gate weights into registers (overlap with input loads)
    float wrm[16], wrs[16];
#pragma unroll
    for (int i = 0; i < 16; i++) {
        wrm[i] = mg_W1[tid + 256 * i];
        wrs[i] = sg_W1[tid + 256 * i];
    }

    // batched, branch-free input loads (56 independent LDGs)
    int m_[BPB], sv_[BPB], si_[BPB], tvv_[BPB], tvi_[BPB], tsv_[BPB], tsi_[BPB];
#pragma unroll
    for (int bi = 0; bi < BPB; bi++) {
        int b = b0 + bi;
        int gt = (b < B ? b : B - 1) * TT + tid;
        m_[bi]   = marker[gt];
        sv_[bi]  = (b < B) ? src_valid[gt] : 0;
        si_[bi]  = src_idx[gt];
        tvv_[bi] = tval_valid[gt];
        tvi_[bi] = tval_idx[gt];
        tsv_[bi] = tsym_valid[gt];
        tsi_[bi] = tsym_idx[gt];
    }
    __syncthreads();

    // build merged compact event lists (register data only)
#pragma unroll
    for (int bi = 0; bi < BPB; bi++) {
        if (sv_[bi] != 0) {
            int si = min(max(si_[bi], 0), SS - 1);
            int m = m_[bi];
            if (m == 1 || m == 2) {
                if (tvv_[bi] != 0) {
                    int tv = min(max(tvi_[bi], 0), VV - 1);
                    int p = atomicAdd(&sCnt[0], 1);
                    sLmap[p] = tid | (bi << 8) | (si << 11) | (tv << 17);
                }
            } else if (m == 3) {
                if (tsv_[bi] != 0) {
                    int ts = min(max(tsi_[bi], 0), SS - 1);
                    int p = atomicAdd(&sCnt[1], 1);
                    sLstep[p] = tid | (bi << 8) | (si << 11) | (ts << 17);
                }
            }
        }
    }

    // store prefetched weights, k-quad interleaved
#pragma unroll
    for (int i = 0; i < 16; i++) {
        int idx = tid + 256 * i;
        int k = idx >> 6, f = idx & 63;
        int dst = (k >> 2) * 256 + (f << 2) + (k & 3);
        sW1m[dst] = wrm[i];
        sW1s[dst] = wrs[i];
    }
    if (tid < DD) {
        sb1m[tid] = mg_b1[tid]; sw2m[tid] = mg_W2[tid];
        sb1s[tid] = sg_b1[tid]; sw2s[tid] = sg_W2[tid];
    }
    __syncthreads();

    const int nmap  = sCnt[0];
    const int nstep = sCnt[1];
    float* sXw = sX + wid * 8 * DD;

    process_events8(sLmap, nmap, mg_b2[0], sGmap, sW1m, sb1m, sw2m,
                    evidence, b0, sXw, lane);
    process_events8(sLstep, nstep, sg_b2[0], sGstep, sW1s, sb1s, sw2s,
                    evidence, b0, sXw, lane);
    __syncthreads();

    // ---- sparse walk: warp bi -> batch bi ----
    {
        const int bi = wid;
        const int b = b0 + bi;
        if (b < B) {
            float* walk = sWalk + bi * SS;
            float* nw   = sNw   + bi * SS;
            float* wsum = sWsum + bi * SS;
            float* accv = sAccv + bi * VV;

            int q = min(max(query_idx[b], 0), SS - 1);
            float qv = (float)query_valid[b];
#pragma unroll
            for (int i = lane; i < SS; i += 32) {
                float w = (i == q) ? qv : 0.f;
                walk[i] = w; wsum[i] = w;
            }
            if (lane < VV) accv[lane] = 0.f;
            __syncwarp();

            for (int it = 0; it < 3; it++) {
#pragma unroll
                for (int i = lane; i < SS; i += 32) nw[i] = 0.f;
                __syncwarp();
                for (int e = lane; e < nstep; e += 32) {
                    int item = sLstep[e];
                    if (((item >> 8) & 7) == bi) {
                        int src = (item >> 11) & 63;
                        int tgt = (item >> 17) & 63;
                        atomicAdd(&nw[tgt], sGstep[e] * walk[src]);
                    }
                }
                __syncwarp();
#pragma unroll
                for (int i = lane; i < SS; i += 32) {
                    float w = nw[i];
                    walk[i] = w; wsum[i] += w;
                }
                __syncwarp();
            }
            for (int e = lane; e < nmap; e += 32) {
                int item = sLmap[e];
                if (((item >> 8) & 7) == bi) {
                    int src = (item >> 11) & 63;
                    int tv  = (item >> 17) & 63;
                    atomicAdd(&accv[tv], sGmap[e] * wsum[src]);
                }
            }
        } else {
            if (lane < VV) sAccv[bi * VV + lane] = 0.f;
#pragma unroll
            for (int i = lane; i < SS; i += 32) sWsum[bi * SS + i] = 0.f;
        }
    }
    __syncthreads();

    // ==== fused heads (register-weight GEMM on transposed states) ====
    // reuse sX: wsT[96][8], gsT[128][8], hT[128][8]
    float* wsT = sX + HT_WS;
    float* gsT = sX + HT_GS;
    float* hT  = sX + HT_H;

    for (int idx = tid; idx < BPB * 96; idx += 256) {
        int bi = idx / 96, j = idx - bi * 96;
        float v = (j < 64) ? sWsum[bi * SS + j] : sAccv[bi * VV + (j - 64)];
        wsT[j * 8 + bi] = v;
    }
    __syncthreads();

    const int col  = tid & 127;
    const int half = tid >> 7;          // 4 batches per half
    const int boff = half * 4;

    // ---- phase A: gs_T[col][bi] ----
    {
        u64 acc0 = 0ull, acc1 = 0ull;
        if (col < DD) {
#pragma unroll 8
            for (int s = 0; s < SS; s++) {
                u64 wd = packdup(__ldg(symbol_emb + s * DD + col));
                const float* row = wsT + s * 8 + boff;
                acc0 = ffma2(*(const u64*)(row),     wd, acc0);
                acc1 = ffma2(*(const u64*)(row + 2), wd, acc1);
            }
        } else {
            const int d = col - DD;
#pragma unroll 8
            for (int v = 0; v < VV; v++) {
                u64 wd = packdup(__ldg(value_emb + v * DD + d));
                const float* row = wsT + (64 + v) * 8 + boff;
                acc0 = ffma2(*(const u64*)(row),     wd, acc0);
                acc1 = ffma2(*(const u64*)(row + 2), wd, acc1);
            }
        }
        float* grow = gsT + col * 8 + boff;
        *(u64*)(grow)     = acc0;
        *(u64*)(grow + 2) = acc1;
    }
    __syncthreads();

    // ---- phase B: h_T[col][bi] = gelu(bias + gs @ W1) ----
    {
        u64 acc0 = 0ull, acc1 = 0ull;
        const float* W1 = (col < DD) ? (oh_W1 + col) : (sf_W1 + col - DD);
#pragma unroll 8
        for (int k = 0; k < 2 * DD; k++) {
            u64 wd = packdup(__ldg(W1 + k * DD));
            const float* row = gsT + k * 8 + boff;
            acc0 = ffma2(*(const u64*)(row),     wd, acc0);
            acc1 = ffma2(*(const u64*)(row + 2), wd, acc1);
        }
        float bias = (col < DD) ? oh_b1[col] : sf_b1[col - DD];
        float* hrow = hT + col * 8 + boff;
        float lo, hi;
        asm("mov.b64 {%0,%1}, %2;" : "=f"(lo), "=f"(hi) : "l"(acc0));
        hrow[0] = gelu_exact(lo + bias);
        hrow[1] = gelu_exact(hi + bias);
        asm("mov.b64 {%0,%1}, %2;" : "=f"(lo), "=f"(hi) : "l"(acc1));
        hrow[2] = gelu_exact(lo + bias);
        hrow[3] = gelu_exact(hi + bias);
    }
    __syncthreads();

    // ---- phase C: outputs (col < 96 per half) ----
    if (col < 96) {
        const int j = col;
        u64 acc0 = 0ull, acc1 = 0ull;
        if (j < VV) {
#pragma unroll 8
            for (int k = 0; k < DD; k++) {
                u64 wd = packdup(__ldg(oh_W2 + k * VV + j));
                const float* row = hT + k * 8 + boff;
                acc0 = ffma2(*(const u64*)(row),     wd, acc0);
                acc1 = ffma2(*(const u64*)(row + 2), wd, acc1);
            }
            float bias = oh_b2[j];
            float lo, hi;
            asm("mov.b64 {%0,%1}, %2;" : "=f"(lo), "=f"(hi) : "l"(acc0));
            int b = b0 + boff;
            if (b < B)     out[(size_t)b * VV + j] = lo + bias;
            if (b + 1 < B) out[(size_t)(b + 1) * VV + j] = hi + bias;
            asm("mov.b64 {%0,%1}, %2;" : "=f"(lo), "=f"(hi) : "l"(acc1));
            if (b + 2 < B) out[(size_t)(b + 2) * VV + j] = lo + bias;
            if (b + 3 < B) out[(size_t)(b + 3) * VV + j] = hi + bias;
        } else {
            const int d = j - VV;
#pragma unroll 8
            for (int k = 0; k < DD; k++) {
                u64 wd = packdup(__ldg(sf_W2 + k * DD + d));
                const float* row = hT + (64 + k) * 8 + boff;
                acc0 = ffma2(*(const u64*)(row),     wd, acc0);
                acc1 = ffma2(*(const u64*)(row + 2), wd, acc1);
            }
            float bias = sf_b2[d];
            float* fb = out + (size_t)B * VV;
            float lo, hi;
            asm("mov.b64 {%0,%1}, %2;" : "=f"(lo), "=f"(hi) : "l"(acc0));
            int b = b0 + boff;
            if (b < B)     fb[(size_t)b * DD + d] = lo + bias;
            if (b + 1 < B) fb[(size_t)(b + 1) * DD + d] = hi + bias;
            asm("mov.b64 {%0,%1}, %2;" : "=f"(lo), "=f"(hi) : "l"(acc1));
            if (b + 2 < B) fb[(size_t)(b + 2) * DD + d] = lo + bias;
            if (b + 3 < B) fb[(size_t)(b + 3) * DD + d] = hi + bias;
        }
    }
}

extern "C" void kernel_launch(void* const* d_in, const int* in_sizes, int n_in,
                              void* d_out, int out_size)
{
    const float* evidence    = (const float*)d_in[0];
    const int*   marker      = (const int*)d_in[1];
    const int*   src_idx     = (const int*)d_in[2];
    const int*   src_valid   = (const int*)d_in[3];
    const int*   tsym_idx    = (const int*)d_in[4];
    const int*   tsym_valid  = (const int*)d_in[5];
    const int*   tval_idx    = (const int*)d_in[6];
    const int*   tval_valid  = (const int*)d_in[7];
    const int*   query_idx   = (const int*)d_in[8];
    const int*   query_valid = (const int*)d_in[9];
    const float* symbol_emb  = (const float*)d_in[10];
    const float* value_emb   = (const float*)d_in[11];
    const float* mg_W1 = (const float*)d_in[12];
    const float* mg_b1 = (const float*)d_in[13];
    const float* mg_W2 = (const float*)d_in[14];
    const float* mg_b2 = (const float*)d_in[15];
    const float* sg_W1 = (const float*)d_in[16];
    const float* sg_b1 = (const float*)d_in[17];
    const float* sg_W2 = (const float*)d_in[18];
    const float* sg_b2 = (const float*)d_in[19];
    const float* sf_W1 = (const float*)d_in[20];
    const float* sf_b1 = (const float*)d_in[21];
    const float* sf_W2 = (const float*)d_in[22];
    const float* sf_b2 = (const float*)d_in[23];
    const float* oh_W1 = (const float*)d_in[24];
    const float* oh_b1 = (const float*)d_in[25];
    const float* oh_W2 = (const float*)d_in[26];
    const float* oh_b2 = (const float*)d_in[27];

    const int B = in_sizes[8];

    const int smem1 = SMEM1_FLOATS * (int)sizeof(float);
    cudaFuncSetAttribute(cpm_fused_kernel, cudaFuncAttributeMaxDynamicSharedMemorySize, smem1);

    const int grid1 = (B + BPB - 1) / BPB;
    cpm_fused_kernel<<<grid1, 256, smem1>>>(
        evidence, marker, src_idx, src_valid, tsym_idx, tsym_valid,
        tval_idx, tval_valid, query_idx, query_valid,
        symbol_emb, value_emb,
        mg_W1, mg_b1, mg_W2, mg_b2,
        sg_W1, sg_b1, sg_W2, sg_b2,
        sf_W1, sf_b1, sf_W2, sf_b2,
        oh_W1, oh_b1, oh_W2, oh_b2,
        (float*)d_out, B);
}

// round 12
// speedup vs baseline: 1.3959x; 1.0572x over previous
#include <cuda_runtime.h>
#include <math.h>

#define TT 256
#define DD 64
#define SS 64
#define VV 32
#define BPB 14           // batches per block -> grid 293 = single wave at 2 CTAs/SM
#define LCAP 3584        // packed list capacity (map front, step back)

typedef unsigned long long u64;

// ---------------- shared layout (floats) ----------------
#define OFF_W1M   0        // 4096 quad-interleaved
#define OFF_W1S   4096     // 4096
#define OFF_B1M   8192     // 64
#define OFF_W2M   8256     // 64
#define OFF_B1S   8320     // 64
#define OFF_W2S   8384     // 64
#define OFF_LIST  8448     // 3584 ints (map front / step back)
#define OFF_GAIN  12032    // 3584 floats (index-aligned with LIST)
#define OFF_X     15616    // 8 warps * 8 tok * 64 = 4096
#define OFF_WALK  19712    // 14*64
#define OFF_NW    20608    // 14*64
#define OFF_WSUM  21504    // 14*64
#define OFF_ACCV  22400    // 14*32
#define OFF_CNT   22848    // 2 ints
#define SMEM_FLOATS 22852  // 91408 bytes

// tail overlay on LIST+GAIN region (7168 floats), stride-16 batch rows
#define HT_WS 0            // 96*16  = 1536
#define HT_GS 1536         // 128*16 = 2048
#define HT_H  3584         // 128*16 = 2048

__device__ __forceinline__ float gelu_exact(float x) {
    return 0.5f * x * (1.0f + erff(x * 0.70710678118654752440f));
}

__device__ __forceinline__ u64 ffma2(u64 a, u64 b, u64 c) {
    u64 d;
    asm("fma.rn.f32x2 %0, %1, %2, %3;" : "=l"(d) : "l"(a), "l"(b), "l"(c));
    return d;
}
__device__ __forceinline__ u64 packdup(float x) {
    u64 d;
    asm("mov.b64 %0, {%1, %1};" : "=l"(d) : "f"(x));
    return d;
}

// warp-cooperative gate MLP, 8 tokens/pass, gather pipelined one pass ahead.
// Quad weight layout: Wq[kq*256 + f*4 + j] = W[4kq+j][f]
// item: tok[0:8) | bi[8:12) | src[12:18) | tgt[18:24)
__device__ __forceinline__ void process_events8(
    const int* __restrict__ list, int n, float b2,
    float* __restrict__ gout,
    const float* __restrict__ sWq, const float* __restrict__ sb1,
    const float* __restrict__ sw2,
    const float* __restrict__ evidence, int b0,
    float* __restrict__ sXw, int lane)
{
    const int wid = threadIdx.x >> 5;
    const int sel = lane >> 4;           // 0: even token of pair, 1: odd
    const int sub = lane & 15;           // 16B chunk within row

    int items[8];
    bool valid[8];
    float4 vreg[4];

    int base = wid * 8;
    if (base < n) {
#pragma unroll
        for (int i = 0; i < 8; i++) {
            int idx = base + i;
            valid[i] = (idx < n);
            items[i] = list[valid[i] ? idx : (n - 1)];
        }
#pragma unroll
        for (int i = 0; i < 8; i += 2) {
            int it = items[i + sel];
            int tok = it & 255;
            int bb  = (it >> 8) & 15;
            vreg[i >> 1] = *((const float4*)(evidence + ((size_t)(b0 + bb) * TT + tok) * DD) + sub);
        }
    }

    for (; base < n; base += 64) {
        // store staged gather for this pass
#pragma unroll
        for (int i = 0; i < 8; i += 2)
            *(float4*)(sXw + (i + sel) * DD + sub * 4) = vreg[i >> 1];
        __syncwarp();

        bool cur_valid[8];
#pragma unroll
        for (int i = 0; i < 8; i++) cur_valid[i] = valid[i];

        // issue gather for next pass (latency covered by FMA loop below)
        int next = base + 64;
        if (next < n) {
#pragma unroll
            for (int i = 0; i < 8; i++) {
                int idx = next + i;
                valid[i] = (idx < n);
                items[i] = list[valid[i] ? idx : (n - 1)];
            }
#pragma unroll
            for (int i = 0; i < 8; i += 2) {
                int it = items[i + sel];
                int tok = it & 255;
                int bb  = (it >> 8) & 15;
                vreg[i >> 1] = *((const float4*)(evidence + ((size_t)(b0 + bb) * TT + tok) * DD) + sub);
            }
        }

        u64 acc0[8], acc1[8];
#pragma unroll
        for (int i = 0; i < 8; i++) { acc0[i] = 0ull; acc1[i] = 0ull; }

#pragma unroll
        for (int kq = 0; kq < DD / 4; kq++) {
            ulonglong2 wa = *(const ulonglong2*)(sWq + kq * 256 + 4 * lane);        // feat l, k-quad
            ulonglong2 wb = *(const ulonglong2*)(sWq + kq * 256 + 128 + 4 * lane);  // feat l+32
#pragma unroll
            for (int i = 0; i < 8; i++) {
                ulonglong2 xq = *(const ulonglong2*)(sXw + i * DD + 4 * kq);  // broadcast LDS.128
                acc0[i] = ffma2(xq.x, wa.x, acc0[i]);
                acc0[i] = ffma2(xq.y, wa.y, acc0[i]);
                acc1[i] = ffma2(xq.x, wb.x, acc1[i]);
                acc1[i] = ffma2(xq.y, wb.y, acc1[i]);
            }
        }

        float b1a = sb1[lane], b1b = sb1[lane + 32];
        float w2a = sw2[lane], w2b = sw2[lane + 32];
#pragma unroll
        for (int i = 0; i < 8; i++) {
            float lo, hi;
            asm("mov.b64 {%0,%1}, %2;" : "=f"(lo), "=f"(hi) : "l"(acc0[i]));
            float h0 = lo + hi + b1a;
            asm("mov.b64 {%0,%1}, %2;" : "=f"(lo), "=f"(hi) : "l"(acc1[i]));
            float h1 = lo + hi + b1b;
            float p = gelu_exact(h0) * w2a + gelu_exact(h1) * w2b;
#pragma unroll
            for (int off = 16; off; off >>= 1)
                p += __shfl_xor_sync(0xffffffffu, p, off);
            if (lane == 0 && cur_valid[i]) {
                gout[base + i] = 1.0f / (1.0f + expf(-(p + b2)));
            }
        }
        __syncwarp();
    }
}

__global__ __launch_bounds__(256, 2)
void cpm_fused_kernel(
    const float* __restrict__ evidence,
    const int* __restrict__ marker,
    const int* __restrict__ src_idx,
    const int* __restrict__ src_valid,
    const int* __restrict__ tsym_idx,
    const int* __restrict__ tsym_valid,
    const int* __restrict__ tval_idx,
    const int* __restrict__ tval_valid,
    const int* __restrict__ query_idx,
    const int* __restrict__ query_valid,
    const float* __restrict__ symbol_emb,
    const float* __restrict__ value_emb,
    const float* __restrict__ mg_W1, const float* __restrict__ mg_b1,
    const float* __restrict__ mg_W2, const float* __restrict__ mg_b2,
    const float* __restrict__ sg_W1, const float* __restrict__ sg_b1,
    const float* __restrict__ sg_W2, const float* __restrict__ sg_b2,
    const float* __restrict__ sf_W1, const float* __restrict__ sf_b1,
    const float* __restrict__ sf_W2, const float* __restrict__ sf_b2,
    const float* __restrict__ oh_W1, const float* __restrict__ oh_b1,
    const float* __restrict__ oh_W2, const float* __restrict__ oh_b2,
    float* __restrict__ out, int B)
{
    extern __shared__ float sm[];
    float* sW1m  = sm + OFF_W1M;
    float* sW1s  = sm + OFF_W1S;
    float* sb1m  = sm + OFF_B1M;
    float* sw2m  = sm + OFF_W2M;
    float* sb1s  = sm + OFF_B1S;
    float* sw2s  = sm + OFF_W2S;
    int*   sList = (int*)(sm + OFF_LIST);
    float* sGain = sm + OFF_GAIN;
    float* sX    = sm + OFF_X;
    float* sWalk = sm + OFF_WALK;
    float* sNw   = sm + OFF_NW;
    float* sWsum = sm + OFF_WSUM;
    float* sAccv = sm + OFF_ACCV;
    int*   sCnt  = (int*)(sm + OFF_CNT);

    const int tid  = threadIdx.x;
    const int lane = tid & 31;
    const int wid  = tid >> 5;
    const int b0   = blockIdx.x * BPB;

    if (tid < 2) sCnt[tid] = 0;

    // prefetch gate weights into registers (overlap with list build)
    float wrm[16], wrs[16];
#pragma unroll
    for (int i = 0; i < 16; i++) {
        wrm[i] = mg_W1[tid + 256 * i];
        wrs[i] = sg_W1[tid + 256 * i];
    }
    __syncthreads();

    // build packed compact event lists (map from front, step from back)
#pragma unroll
    for (int bi = 0; bi < BPB; bi++) {
        const int b = b0 + bi;
        if (b >= B) break;
        const int gt = b * TT + tid;
        int m  = marker[gt];
        int sv = src_valid[gt];
        if (sv != 0) {
            int si = min(max(src_idx[gt], 0), SS - 1);
            if (m == 1 || m == 2) {
                if (tval_valid[gt] != 0) {
                    int tv = min(max(tval_idx[gt], 0), VV - 1);
                    int p = atomicAdd(&sCnt[0], 1);
                    sList[p] = tid | (bi << 8) | (si << 12) | (tv << 18);
                }
            } else if (m == 3) {
                if (tsym_valid[gt] != 0) {
                    int ts = min(max(tsym_idx[gt], 0), SS - 1);
                    int p = atomicAdd(&sCnt[1], 1);
                    sList[LCAP - 1 - p] = tid | (bi << 8) | (si << 12) | (ts << 18);
                }
            }
        }
    }

    // store prefetched weights, k-quad interleaved
#pragma unroll
    for (int i = 0; i < 16; i++) {
        int idx = tid + 256 * i;
        int k = idx >> 6, f = idx & 63;
        int dst = (k >> 2) * 256 + (f << 2) + (k & 3);
        sW1m[dst] = wrm[i];
        sW1s[dst] = wrs[i];
    }
    if (tid < DD) {
        sb1m[tid] = mg_b1[tid]; sw2m[tid] = mg_W2[tid];
        sb1s[tid] = sg_b1[tid]; sw2s[tid] = sg_W2[tid];
    }
    __syncthreads();

    const int nmap  = sCnt[0];
    const int nstep = sCnt[1];
    const int*   lstep = sList + LCAP - nstep;
    float*       gstep = sGain + LCAP - nstep;
    float* sXw = sX + wid * 8 * DD;

    process_events8(sList, nmap, mg_b2[0], sGain, sW1m, sb1m, sw2m,
                    evidence, b0, sXw, lane);
    process_events8(lstep, nstep, sg_b2[0], gstep, sW1s, sb1s, sw2s,
                    evidence, b0, sXw, lane);
    __syncthreads();

    // ---- sparse walk: warps cover 14 batches in two rounds ----
#pragma unroll
    for (int ph = 0; ph < 2; ph++) {
        const int bi = wid + ph * 8;
        if (bi < BPB) {
            const int b = b0 + bi;
            float* walk = sWalk + bi * SS;
            float* nw   = sNw   + bi * SS;
            float* wsum = sWsum + bi * SS;
            float* accv = sAccv + bi * VV;
            if (b < B) {
                int q = min(max(query_idx[b], 0), SS - 1);
                float qv = (float)query_valid[b];
#pragma unroll
                for (int i = lane; i < SS; i += 32) {
                    float w = (i == q) ? qv : 0.f;
                    walk[i] = w; wsum[i] = w;
                }
                if (lane < VV) accv[lane] = 0.f;
                __syncwarp();

                for (int it = 0; it < 3; it++) {
#pragma unroll
                    for (int i = lane; i < SS; i += 32) nw[i] = 0.f;
                    __syncwarp();
                    for (int e = lane; e < nstep; e += 32) {
                        int item = lstep[e];
                        if (((item >> 8) & 15) == bi) {
                            int src = (item >> 12) & 63;
                            int tgt = (item >> 18) & 63;
                            atomicAdd(&nw[tgt], gstep[e] * walk[src]);
                        }
                    }
                    __syncwarp();
#pragma unroll
                    for (int i = lane; i < SS; i += 32) {
                        float w = nw[i];
                        walk[i] = w; wsum[i] += w;
                    }
                    __syncwarp();
                }
                for (int e = lane; e < nmap; e += 32) {
                    int item = sList[e];
                    if (((item >> 8) & 15) == bi) {
                        int src = (item >> 12) & 63;
                        int tv  = (item >> 18) & 63;
                        atomicAdd(&accv[tv], sGain[e] * wsum[src]);
                    }
                }
            } else {
                if (lane < VV) accv[lane] = 0.f;
#pragma unroll
                for (int i = lane; i < SS; i += 32) wsum[i] = 0.f;
            }
        }
    }
    __syncthreads();

    // ==== fused heads: overlay transposed states on dead list/gain region ====
    float* wsT = sm + OFF_LIST + HT_WS;   // [96][16]
    float* gsT = sm + OFF_LIST + HT_GS;   // [128][16]
    float* hT  = sm + OFF_LIST + HT_H;    // [128][16]

    for (int idx = tid; idx < 96 * 16; idx += 256) {
        int j = idx >> 4, bi = idx & 15;
        float v = 0.f;
        if (bi < BPB)
            v = (j < 64) ? sWsum[bi * SS + j] : sAccv[bi * VV + (j - 64)];
        wsT[j * 16 + bi] = v;
    }
    __syncthreads();

    const int col  = tid & 127;
    const int half = tid >> 7;          // 8 batch-slots per half
    const int boff = half * 8;

    // ---- phase A: gs_T[col][bi] ----
    {
        u64 acc[4] = {0ull, 0ull, 0ull, 0ull};
        if (col < DD) {
#pragma unroll 8
            for (int s = 0; s < SS; s++) {
                u64 wd = packdup(__ldg(symbol_emb + s * DD + col));
                const float* row = wsT + s * 16 + boff;
#pragma unroll
                for (int p = 0; p < 4; p++)
                    acc[p] = ffma2(*(const u64*)(row + 2 * p), wd, acc[p]);
            }
        } else {
            const int d = col - DD;
#pragma unroll 8
            for (int v = 0; v < VV; v++) {
                u64 wd = packdup(__ldg(value_emb + v * DD + d));
                const float* row = wsT + (64 + v) * 16 + boff;
#pragma unroll
                for (int p = 0; p < 4; p++)
                    acc[p] = ffma2(*(const u64*)(row + 2 * p), wd, acc[p]);
            }
        }
        float* grow = gsT + col * 16 + boff;
#pragma unroll
        for (int p = 0; p < 4; p++) *(u64*)(grow + 2 * p) = acc[p];
    }
    __syncthreads();

    // ---- phase B: h_T[col][bi] = gelu(bias + gs @ W1) ----
    {
        u64 acc[4] = {0ull, 0ull, 0ull, 0ull};
        const float* W1 = (col < DD) ? (oh_W1 + col) : (sf_W1 + col - DD);
#pragma unroll 8
        for (int k = 0; k < 2 * DD; k++) {
            u64 wd = packdup(__ldg(W1 + k * DD));
            const float* row = gsT + k * 16 + boff;
#pragma unroll
            for (int p = 0; p < 4; p++)
                acc[p] = ffma2(*(const u64*)(row + 2 * p), wd, acc[p]);
        }
        float bias = (col < DD) ? oh_b1[col] : sf_b1[col - DD];
        float* hrow = hT + col * 16 + boff;
#pragma unroll
        for (int p = 0; p < 4; p++) {
            float lo, hi;
            asm("mov.b64 {%0,%1}, %2;" : "=f"(lo), "=f"(hi) : "l"(acc[p]));
            hrow[2 * p]     = gelu_exact(lo + bias);
            hrow[2 * p + 1] = gelu_exact(hi + bias);
        }
    }
    __syncthreads();

    // ---- phase C: outputs (col < 96 per half) ----
    if (col < 96) {
        const int j = col;
        u64 acc[4] = {0ull, 0ull, 0ull, 0ull};
        if (j < VV) {
#pragma unroll 8
            for (int k = 0; k < DD; k++) {
                u64 wd = packdup(__ldg(oh_W2 + k * VV + j));
                const float* row = hT + k * 16 + boff;
#pragma unroll
                for (int p = 0; p < 4; p++)
                    acc[p] = ffma2(*(const u64*)(row + 2 * p), wd, acc[p]);
            }
            float bias = oh_b2[j];
#pragma unroll
            for (int p = 0; p < 4; p++) {
                float lo, hi;
                asm("mov.b64 {%0,%1}, %2;" : "=f"(lo), "=f"(hi) : "l"(acc[p]));
                int bi0 = boff + 2 * p;
                int b = b0 + bi0;
                if (bi0 < BPB && b < B)         out[(size_t)b * VV + j] = lo + bias;
                if (bi0 + 1 < BPB && b + 1 < B) out[(size_t)(b + 1) * VV + j] = hi + bias;
            }
        } else {
            const int d = j - VV;
#pragma unroll 8
            for (int k = 0; k < DD; k++) {
                u64 wd = packdup(__ldg(sf_W2 + k * DD + d));
                const float* row = hT + (64 + k) * 16 + boff;
#pragma unroll
                for (int p = 0; p < 4; p++)
                    acc[p] = ffma2(*(const u64*)(row + 2 * p), wd, acc[p]);
            }
            float bias = sf_b2[d];
            float* fb = out + (size_t)B * VV;
#pragma unroll
            for (int p = 0; p < 4; p++) {
                float lo, hi;
                asm("mov.b64 {%0,%1}, %2;" : "=f"(lo), "=f"(hi) : "l"(acc[p]));
                int bi0 = boff + 2 * p;
                int b = b0 + bi0;
                if (bi0 < BPB && b < B)         fb[(size_t)b * DD + d] = lo + bias;
                if (bi0 + 1 < BPB && b + 1 < B) fb[(size_t)(b + 1) * DD + d] = hi + bias;
            }
        }
    }
}

extern "C" void kernel_launch(void* const* d_in, const int* in_sizes, int n_in,
                              void* d_out, int out_size)
{
    const float* evidence    = (const float*)d_in[0];
    const int*   marker      = (const int*)d_in[1];
    const int*   src_idx     = (const int*)d_in[2];
    const int*   src_valid   = (const int*)d_in[3];
    const int*   tsym_idx    = (const int*)d_in[4];
    const int*   tsym_valid  = (const int*)d_in[5];
    const int*   tval_idx    = (const int*)d_in[6];
    const int*   tval_valid  = (const int*)d_in[7];
    const int*   query_idx   = (const int*)d_in[8];
    const int*   query_valid = (const int*)d_in[9];
    const float* symbol_emb  = (const float*)d_in[10];
    const float* value_emb   = (const float*)d_in[11];
    const float* mg_W1 = (const float*)d_in[12];
    const float* mg_b1 = (const float*)d_in[13];
    const float* mg_W2 = (const float*)d_in[14];
    const float* mg_b2 = (const float*)d_in[15];
    const float* sg_W1 = (const float*)d_in[16];
    const float* sg_b1 = (const float*)d_in[17];
    const float* sg_W2 = (const float*)d_in[18];
    const float* sg_b2 = (const float*)d_in[19];
    const float* sf_W1 = (const float*)d_in[20];
    const float* sf_b1 = (const float*)d_in[21];
    const float* sf_W2 = (const float*)d_in[22];
    const float* sf_b2 = (const float*)d_in[23];
    const float* oh_W1 = (const float*)d_in[24];
    const float* oh_b1 = (const float*)d_in[25];
    const float* oh_W2 = (const float*)d_in[26];
    const float* oh_b2 = (const float*)d_in[27];

    const int B = in_sizes[8];

    const int smem = SMEM_FLOATS * (int)sizeof(float);
    cudaFuncSetAttribute(cpm_fused_kernel, cudaFuncAttributeMaxDynamicSharedMemorySize, smem);

    const int grid = (B + BPB - 1) / BPB;
    cpm_fused_kernel<<<grid, 256, smem>>>(
        evidence, marker, src_idx, src_valid, tsym_idx, tsym_valid,
        tval_idx, tval_valid, query_idx, query_valid,
        symbol_emb, value_emb,
        mg_W1, mg_b1, mg_W2, mg_b2,
        sg_W1, sg_b1, sg_W2, sg_b2,
        sf_W1, sf_b1, sf_W2, sf_b2,
        oh_W1, oh_b1, oh_W2, oh_b2,
        (float*)d_out, B);
}

// round 13
// speedup vs baseline: 1.5385x; 1.1022x over previous
#include <cuda_runtime.h>
#include <math.h>

#define TT 256
#define DD 64
#define SS 64
#define VV 32
#define BPB 14           // batches per block -> grid 293 = single wave at 2 CTAs/SM
#define LCAP 3584        // packed list capacity (map front, step back)

typedef unsigned long long u64;

// ---------------- shared layout (floats) ----------------
#define OFF_W1M   0        // 4096 quad-interleaved
#define OFF_W1S   4096     // 4096
#define OFF_B1M   8192     // 64
#define OFF_W2M   8256     // 64
#define OFF_B1S   8320     // 64
#define OFF_W2S   8384     // 64
#define OFF_LIST  8448     // 3584 ints (map front / step back)
#define OFF_GAIN  12032    // 3584 floats (index-aligned with LIST)
#define OFF_X     15616    // 8 warps * 8 tok * 64 = 4096
#define OFF_WALK  19712    // 14*64
#define OFF_NW    20608    // 14*64
#define OFF_WSUM  21504    // 14*64
#define OFF_ACCV  22400    // 14*32
#define OFF_CNT   22848    // 2 ints
#define SMEM_FLOATS 22852  // 91408 bytes

// tail overlay on LIST+GAIN region (7168 floats), stride-16 batch rows
#define HT_WS 0            // 96*16  = 1536
#define HT_GS 1536         // 128*16 = 2048
#define HT_H  3584         // 128*16 = 2048

// tanh-form GELU with single-instruction MUFU.TANH.
// |h| <~ 1.6 in this workload -> abs err vs exact gelu <= ~1e-4; final rel err ~1e-4 << 1e-3.
__device__ __forceinline__ float gelu_fast(float x) {
    float x2 = x * x;
    float inner = x * fmaf(0.044715f, x2, 1.0f);
    float arg = 0.79788456080286535588f * inner;
    float th;
    asm("tanh.approx.f32 %0, %1;" : "=f"(th) : "f"(arg));
    return 0.5f * x * (1.0f + th);
}

__device__ __forceinline__ u64 ffma2(u64 a, u64 b, u64 c) {
    u64 d;
    asm("fma.rn.f32x2 %0, %1, %2, %3;" : "=l"(d) : "l"(a), "l"(b), "l"(c));
    return d;
}
__device__ __forceinline__ u64 packdup(float x) {
    u64 d;
    asm("mov.b64 %0, {%1, %1};" : "=l"(d) : "f"(x));
    return d;
}

// warp-cooperative gate MLP, 8 tokens/pass, gather pipelined one pass ahead.
// Quad weight layout: Wq[kq*256 + f*4 + j] = W[4kq+j][f]
// item: tok[0:8) | bi[8:12) | src[12:18) | tgt[18:24)
__device__ __forceinline__ void process_events8(
    const int* __restrict__ list, int n, float b2,
    float* __restrict__ gout,
    const float* __restrict__ sWq, const float* __restrict__ sb1,
    const float* __restrict__ sw2,
    const float* __restrict__ evidence, int b0,
    float* __restrict__ sXw, int lane)
{
    const int wid = threadIdx.x >> 5;
    const int sel = lane >> 4;           // 0: even token of pair, 1: odd
    const int sub = lane & 15;           // 16B chunk within row

    int items[8];
    bool valid[8];
    float4 vreg[4];

    int base = wid * 8;
    if (base < n) {
#pragma unroll
        for (int i = 0; i < 8; i++) {
            int idx = base + i;
            valid[i] = (idx < n);
            items[i] = list[valid[i] ? idx : (n - 1)];
        }
#pragma unroll
        for (int i = 0; i < 8; i += 2) {
            int it = items[i + sel];
            int tok = it & 255;
            int bb  = (it >> 8) & 15;
            vreg[i >> 1] = *((const float4*)(evidence + ((size_t)(b0 + bb) * TT + tok) * DD) + sub);
        }
    }

    for (; base < n; base += 64) {
        // store staged gather for this pass
#pragma unroll
        for (int i = 0; i < 8; i += 2)
            *(float4*)(sXw + (i + sel) * DD + sub * 4) = vreg[i >> 1];
        __syncwarp();

        bool cur_valid[8];
#pragma unroll
        for (int i = 0; i < 8; i++) cur_valid[i] = valid[i];

        // issue gather for next pass (latency covered by FMA loop below)
        int next = base + 64;
        if (next < n) {
#pragma unroll
            for (int i = 0; i < 8; i++) {
                int idx = next + i;
                valid[i] = (idx < n);
                items[i] = list[valid[i] ? idx : (n - 1)];
            }
#pragma unroll
            for (int i = 0; i < 8; i += 2) {
                int it = items[i + sel];
                int tok = it & 255;
                int bb  = (it >> 8) & 15;
                vreg[i >> 1] = *((const float4*)(evidence + ((size_t)(b0 + bb) * TT + tok) * DD) + sub);
            }
        }

        u64 acc0[8], acc1[8];
#pragma unroll
        for (int i = 0; i < 8; i++) { acc0[i] = 0ull; acc1[i] = 0ull; }

#pragma unroll
        for (int kq = 0; kq < DD / 4; kq++) {
            ulonglong2 wa = *(const ulonglong2*)(sWq + kq * 256 + 4 * lane);        // feat l, k-quad
            ulonglong2 wb = *(const ulonglong2*)(sWq + kq * 256 + 128 + 4 * lane);  // feat l+32
#pragma unroll
            for (int i = 0; i < 8; i++) {
                ulonglong2 xq = *(const ulonglong2*)(sXw + i * DD + 4 * kq);  // broadcast LDS.128
                acc0[i] = ffma2(xq.x, wa.x, acc0[i]);
                acc0[i] = ffma2(xq.y, wa.y, acc0[i]);
                acc1[i] = ffma2(xq.x, wb.x, acc1[i]);
                acc1[i] = ffma2(xq.y, wb.y, acc1[i]);
            }
        }

        float b1a = sb1[lane], b1b = sb1[lane + 32];
        float w2a = sw2[lane], w2b = sw2[lane + 32];
#pragma unroll
        for (int i = 0; i < 8; i++) {
            float lo, hi;
            asm("mov.b64 {%0,%1}, %2;" : "=f"(lo), "=f"(hi) : "l"(acc0[i]));
            float h0 = lo + hi + b1a;
            asm("mov.b64 {%0,%1}, %2;" : "=f"(lo), "=f"(hi) : "l"(acc1[i]));
            float h1 = lo + hi + b1b;
            float p = gelu_fast(h0) * w2a + gelu_fast(h1) * w2b;
#pragma unroll
            for (int off = 16; off; off >>= 1)
                p += __shfl_xor_sync(0xffffffffu, p, off);
            if (lane == 0 && cur_valid[i]) {
                gout[base + i] = 1.0f / (1.0f + __expf(-(p + b2)));
            }
        }
        __syncwarp();
    }
}

__global__ __launch_bounds__(256, 2)
void cpm_fused_kernel(
    const float* __restrict__ evidence,
    const int* __restrict__ marker,
    const int* __restrict__ src_idx,
    const int* __restrict__ src_valid,
    const int* __restrict__ tsym_idx,
    const int* __restrict__ tsym_valid,
    const int* __restrict__ tval_idx,
    const int* __restrict__ tval_valid,
    const int* __restrict__ query_idx,
    const int* __restrict__ query_valid,
    const float* __restrict__ symbol_emb,
    const float* __restrict__ value_emb,
    const float* __restrict__ mg_W1, const float* __restrict__ mg_b1,
    const float* __restrict__ mg_W2, const float* __restrict__ mg_b2,
    const float* __restrict__ sg_W1, const float* __restrict__ sg_b1,
    const float* __restrict__ sg_W2, const float* __restrict__ sg_b2,
    const float* __restrict__ sf_W1, const float* __restrict__ sf_b1,
    const float* __restrict__ sf_W2, const float* __restrict__ sf_b2,
    const float* __restrict__ oh_W1, const float* __restrict__ oh_b1,
    const float* __restrict__ oh_W2, const float* __restrict__ oh_b2,
    float* __restrict__ out, int B)
{
    extern __shared__ float sm[];
    float* sW1m  = sm + OFF_W1M;
    float* sW1s  = sm + OFF_W1S;
    float* sb1m  = sm + OFF_B1M;
    float* sw2m  = sm + OFF_W2M;
    float* sb1s  = sm + OFF_B1S;
    float* sw2s  = sm + OFF_W2S;
    int*   sList = (int*)(sm + OFF_LIST);
    float* sGain = sm + OFF_GAIN;
    float* sX    = sm + OFF_X;
    float* sWalk = sm + OFF_WALK;
    float* sNw   = sm + OFF_NW;
    float* sWsum = sm + OFF_WSUM;
    float* sAccv = sm + OFF_ACCV;
    int*   sCnt  = (int*)(sm + OFF_CNT);

    const int tid  = threadIdx.x;
    const int lane = tid & 31;
    const int wid  = tid >> 5;
    const int b0   = blockIdx.x * BPB;

    if (tid < 2) sCnt[tid] = 0;

    // prefetch gate weights into registers (overlap with list build)
    float wrm[16], wrs[16];
#pragma unroll
    for (int i = 0; i < 16; i++) {
        wrm[i] = mg_W1[tid + 256 * i];
        wrs[i] = sg_W1[tid + 256 * i];
    }
    __syncthreads();

    // build packed compact event lists (map from front, step from back)
#pragma unroll
    for (int bi = 0; bi < BPB; bi++) {
        const int b = b0 + bi;
        if (b >= B) break;
        const int gt = b * TT + tid;
        int m  = marker[gt];
        int sv = src_valid[gt];
        if (sv != 0) {
            int si = min(max(src_idx[gt], 0), SS - 1);
            if (m == 1 || m == 2) {
                if (tval_valid[gt] != 0) {
                    int tv = min(max(tval_idx[gt], 0), VV - 1);
                    int p = atomicAdd(&sCnt[0], 1);
                    sList[p] = tid | (bi << 8) | (si << 12) | (tv << 18);
                }
            } else if (m == 3) {
                if (tsym_valid[gt] != 0) {
                    int ts = min(max(tsym_idx[gt], 0), SS - 1);
                    int p = atomicAdd(&sCnt[1], 1);
                    sList[LCAP - 1 - p] = tid | (bi << 8) | (si << 12) | (ts << 18);
                }
            }
        }
    }

    // store prefetched weights, k-quad interleaved
#pragma unroll
    for (int i = 0; i < 16; i++) {
        int idx = tid + 256 * i;
        int k = idx >> 6, f = idx & 63;
        int dst = (k >> 2) * 256 + (f << 2) + (k & 3);
        sW1m[dst] = wrm[i];
        sW1s[dst] = wrs[i];
    }
    if (tid < DD) {
        sb1m[tid] = mg_b1[tid]; sw2m[tid] = mg_W2[tid];
        sb1s[tid] = sg_b1[tid]; sw2s[tid] = sg_W2[tid];
    }
    __syncthreads();

    const int nmap  = sCnt[0];
    const int nstep = sCnt[1];
    const int*   lstep = sList + LCAP - nstep;
    float*       gstep = sGain + LCAP - nstep;
    float* sXw = sX + wid * 8 * DD;

    process_events8(sList, nmap, mg_b2[0], sGain, sW1m, sb1m, sw2m,
                    evidence, b0, sXw, lane);
    process_events8(lstep, nstep, sg_b2[0], gstep, sW1s, sb1s, sw2s,
                    evidence, b0, sXw, lane);
    __syncthreads();

    // ---- sparse walk: warps cover 14 batches in two rounds ----
#pragma unroll
    for (int ph = 0; ph < 2; ph++) {
        const int bi = wid + ph * 8;
        if (bi < BPB) {
            const int b = b0 + bi;
            float* walk = sWalk + bi * SS;
            float* nw   = sNw   + bi * SS;
            float* wsum = sWsum + bi * SS;
            float* accv = sAccv + bi * VV;
            if (b < B) {
                int q = min(max(query_idx[b], 0), SS - 1);
                float qv = (float)query_valid[b];
#pragma unroll
                for (int i = lane; i < SS; i += 32) {
                    float w = (i == q) ? qv : 0.f;
                    walk[i] = w; wsum[i] = w;
                }
                if (lane < VV) accv[lane] = 0.f;
                __syncwarp();

                for (int it = 0; it < 3; it++) {
#pragma unroll
                    for (int i = lane; i < SS; i += 32) nw[i] = 0.f;
                    __syncwarp();
                    for (int e = lane; e < nstep; e += 32) {
                        int item = lstep[e];
                        if (((item >> 8) & 15) == bi) {
                            int src = (item >> 12) & 63;
                            int tgt = (item >> 18) & 63;
                            atomicAdd(&nw[tgt], gstep[e] * walk[src]);
                        }
                    }
                    __syncwarp();
#pragma unroll
                    for (int i = lane; i < SS; i += 32) {
                        float w = nw[i];
                        walk[i] = w; wsum[i] += w;
                    }
                    __syncwarp();
                }
                for (int e = lane; e < nmap; e += 32) {
                    int item = sList[e];
                    if (((item >> 8) & 15) == bi) {
                        int src = (item >> 12) & 63;
                        int tv  = (item >> 18) & 63;
                        atomicAdd(&accv[tv], sGain[e] * wsum[src]);
                    }
                }
            } else {
                if (lane < VV) accv[lane] = 0.f;
#pragma unroll
                for (int i = lane; i < SS; i += 32) wsum[i] = 0.f;
            }
        }
    }
    __syncthreads();

    // ==== fused heads: overlay transposed states on dead list/gain region ====
    float* wsT = sm + OFF_LIST + HT_WS;   // [96][16]
    float* gsT = sm + OFF_LIST + HT_GS;   // [128][16]
    float* hT  = sm + OFF_LIST + HT_H;    // [128][16]

    for (int idx = tid; idx < 96 * 16; idx += 256) {
        int j = idx >> 4, bi = idx & 15;
        float v = 0.f;
        if (bi < BPB)
            v = (j < 64) ? sWsum[bi * SS + j] : sAccv[bi * VV + (j - 64)];
        wsT[j * 16 + bi] = v;
    }
    __syncthreads();

    const int col  = tid & 127;
    const int half = tid >> 7;          // 8 batch-slots per half
    const int boff = half * 8;

    // ---- phase A: gs_T[col][bi] ----
    {
        u64 acc[4] = {0ull, 0ull, 0ull, 0ull};
        if (col < DD) {
#pragma unroll 8
            for (int s = 0; s < SS; s++) {
                u64 wd = packdup(__ldg(symbol_emb + s * DD + col));
                const float* row = wsT + s * 16 + boff;
#pragma unroll
                for (int p = 0; p < 4; p++)
                    acc[p] = ffma2(*(const u64*)(row + 2 * p), wd, acc[p]);
            }
        } else {
            const int d = col - DD;
#pragma unroll 8
            for (int v = 0; v < VV; v++) {
                u64 wd = packdup(__ldg(value_emb + v * DD + d));
                const float* row = wsT + (64 + v) * 16 + boff;
#pragma unroll
                for (int p = 0; p < 4; p++)
                    acc[p] = ffma2(*(const u64*)(row + 2 * p), wd, acc[p]);
            }
        }
        float* grow = gsT + col * 16 + boff;
#pragma unroll
        for (int p = 0; p < 4; p++) *(u64*)(grow + 2 * p) = acc[p];
    }
    __syncthreads();

    // ---- phase B: h_T[col][bi] = gelu(bias + gs @ W1) ----
    // NOTE: head hidden activations can exceed the gate-MLP range, but stay
    // well within tanh-gelu's ~1e-3 abs worst case; tolerance analysis holds.
    {
        u64 acc[4] = {0ull, 0ull, 0ull, 0ull};
        const float* W1 = (col < DD) ? (oh_W1 + col) : (sf_W1 + col - DD);
#pragma unroll 8
        for (int k = 0; k < 2 * DD; k++) {
            u64 wd = packdup(__ldg(W1 + k * DD));
            const float* row = gsT + k * 16 + boff;
#pragma unroll
            for (int p = 0; p < 4; p++)
                acc[p] = ffma2(*(const u64*)(row + 2 * p), wd, acc[p]);
        }
        float bias = (col < DD) ? oh_b1[col] : sf_b1[col - DD];
        float* hrow = hT + col * 16 + boff;
#pragma unroll
        for (int p = 0; p < 4; p++) {
            float lo, hi;
            asm("mov.b64 {%0,%1}, %2;" : "=f"(lo), "=f"(hi) : "l"(acc[p]));
            hrow[2 * p]     = gelu_fast(lo + bias);
            hrow[2 * p + 1] = gelu_fast(hi + bias);
        }
    }
    __syncthreads();

    // ---- phase C: outputs (col < 96 per half) ----
    if (col < 96) {
        const int j = col;
        u64 acc[4] = {0ull, 0ull, 0ull, 0ull};
        if (j < VV) {
#pragma unroll 8
            for (int k = 0; k < DD; k++) {
                u64 wd = packdup(__ldg(oh_W2 + k * VV + j));
                const float* row = hT + k * 16 + boff;
#pragma unroll
                for (int p = 0; p < 4; p++)
                    acc[p] = ffma2(*(const u64*)(row + 2 * p), wd, acc[p]);
            }
            float bias = oh_b2[j];
#pragma unroll
            for (int p = 0; p < 4; p++) {
                float lo, hi;
                asm("mov.b64 {%0,%1}, %2;" : "=f"(lo), "=f"(hi) : "l"(acc[p]));
                int bi0 = boff + 2 * p;
                int b = b0 + bi0;
                if (bi0 < BPB && b < B)         out[(size_t)b * VV + j] = lo + bias;
                if (bi0 + 1 < BPB && b + 1 < B) out[(size_t)(b + 1) * VV + j] = hi + bias;
            }
        } else {
            const int d = j - VV;
#pragma unroll 8
            for (int k = 0; k < DD; k++) {
                u64 wd = packdup(__ldg(sf_W2 + k * DD + d));
                const float* row = hT + (64 + k) * 16 + boff;
#pragma unroll
                for (int p = 0; p < 4; p++)
                    acc[p] = ffma2(*(const u64*)(row + 2 * p), wd, acc[p]);
            }
            float bias = sf_b2[d];
            float* fb = out + (size_t)B * VV;
#pragma unroll
            for (int p = 0; p < 4; p++) {
                float lo, hi;
                asm("mov.b64 {%0,%1}, %2;" : "=f"(lo), "=f"(hi) : "l"(acc[p]));
                int bi0 = boff + 2 * p;
                int b = b0 + bi0;
                if (bi0 < BPB && b < B)         fb[(size_t)b * DD + d] = lo + bias;
                if (bi0 + 1 < BPB && b + 1 < B) fb[(size_t)(b + 1) * DD + d] = hi + bias;
            }
        }
    }
}

extern "C" void kernel_launch(void* const* d_in, const int* in_sizes, int n_in,
                              void* d_out, int out_size)
{
    const float* evidence    = (const float*)d_in[0];
    const int*   marker      = (const int*)d_in[1];
    const int*   src_idx     = (const int*)d_in[2];
    const int*   src_valid   = (const int*)d_in[3];
    const int*   tsym_idx    = (const int*)d_in[4];
    const int*   tsym_valid  = (const int*)d_in[5];
    const int*   tval_idx    = (const int*)d_in[6];
    const int*   tval_valid  = (const int*)d_in[7];
    const int*   query_idx   = (const int*)d_in[8];
    const int*   query_valid = (const int*)d_in[9];
    const float* symbol_emb  = (const float*)d_in[10];
    const float* value_emb   = (const float*)d_in[11];
    const float* mg_W1 = (const float*)d_in[12];
    const float* mg_b1 = (const float*)d_in[13];
    const float* mg_W2 = (const float*)d_in[14];
    const float* mg_b2 = (const float*)d_in[15];
    const float* sg_W1 = (const float*)d_in[16];
    const float* sg_b1 = (const float*)d_in[17];
    const float* sg_W2 = (const float*)d_in[18];
    const float* sg_b2 = (const float*)d_in[19];
    const float* sf_W1 = (const float*)d_in[20];
    const float* sf_b1 = (const float*)d_in[21];
    const float* sf_W2 = (const float*)d_in[22];
    const float* sf_b2 = (const float*)d_in[23];
    const float* oh_W1 = (const float*)d_in[24];
    const float* oh_b1 = (const float*)d_in[25];
    const float* oh_W2 = (const float*)d_in[26];
    const float* oh_b2 = (const float*)d_in[27];

    const int B = in_sizes[8];

    const int smem = SMEM_FLOATS * (int)sizeof(float);
    cudaFuncSetAttribute(cpm_fused_kernel, cudaFuncAttributeMaxDynamicSharedMemorySize, smem);

    const int grid = (B + BPB - 1) / BPB;
    cpm_fused_kernel<<<grid, 256, smem>>>(
        evidence, marker, src_idx, src_valid, tsym_idx, tsym_valid,
        tval_idx, tval_valid, query_idx, query_valid,
        symbol_emb, value_emb,
        mg_W1, mg_b1, mg_W2, mg_b2,
        sg_W1, sg_b1, sg_W2, sg_b2,
        sf_W1, sf_b1, sf_W2, sf_b2,
        oh_W1, oh_b1, oh_W2, oh_b2,
        (float*)d_out, B);
}